// round 14
// baseline (speedup 1.0000x reference)
#include <cstdint>
#include <cstddef>
#include <cuda_runtime.h>
#include <cuda_bf16.h>
#include <math.h>

#define Bb   2
#define Tt   1024
#define Cc   768
#define Hh   12
#define HID  3072
#define NFCG 6144
#define Mrows (Bb*Tt)          // 2048

// part region offsets (floats)
#define PART_QKV  0            // 12*2304
#define PART_AO   27648        // 12*768
#define PART_FCG  36864        // 12*6144
#define PART_PROJ 110592       // 48*768
#define PART_TOT  147456

// ---------------- scratch (static device arrays; no cudaMalloc) ----------------
__device__ float g_x1  [Mrows*Cc];
__device__ float g_rn  [Mrows];
__device__ float g_part[PART_TOT];
__device__ float g_rope[Tt*64];
__device__ __nv_bfloat16 g_qkvb[Mrows*3*Cc];
__device__ __nv_bfloat16 g_h   [Mrows*Cc];
__device__ __nv_bfloat16 g_o   [Mrows*Cc];
__device__ __nv_bfloat16 g_h2  [Mrows*Cc];
__device__ __nv_bfloat16 g_u   [Mrows*HID];
__device__ __nv_bfloat16 g_wq  [Cc*3*Cc];
__device__ __nv_bfloat16 g_wao [Cc*Cc];
__device__ __nv_bfloat16 g_wfcg[Cc*NFCG];      // interleaved: col 2j=fc_j, 2j+1=gate_j
__device__ __nv_bfloat16 g_wp  [HID*Cc];

// ---------------- helpers ------------------------------------------------------
__device__ __forceinline__ float blockReduceSum(float v) {
    __shared__ float sh[8];
    int lane = threadIdx.x & 31, w = threadIdx.x >> 5;
    #pragma unroll
    for (int o = 16; o; o >>= 1) v += __shfl_xor_sync(0xffffffffu, v, o);
    __syncthreads();
    if (lane == 0) sh[w] = v;
    __syncthreads();
    return sh[0]+sh[1]+sh[2]+sh[3]+sh[4]+sh[5]+sh[6]+sh[7];
}

__device__ __forceinline__ void blockReduceSum2(float& a, float& b) {
    __shared__ float sha[8], shb[8];
    int lane = threadIdx.x & 31, w = threadIdx.x >> 5;
    #pragma unroll
    for (int o = 16; o; o >>= 1) {
        a += __shfl_xor_sync(0xffffffffu, a, o);
        b += __shfl_xor_sync(0xffffffffu, b, o);
    }
    __syncthreads();
    if (lane == 0) { sha[w] = a; shb[w] = b; }
    __syncthreads();
    a = sha[0]+sha[1]+sha[2]+sha[3]+sha[4]+sha[5]+sha[6]+sha[7];
    b = shb[0]+shb[1]+shb[2]+shb[3]+shb[4]+shb[5]+shb[6]+shb[7];
}

__device__ __forceinline__ float gelu_tanh(float x) {
    float x3 = x * x * x;
    float t  = tanhf(0.7978845608028654f * (x + 0.044715f * x3));
    return 0.5f * x * (1.0f + t);
}

__device__ __forceinline__ float to_f32(float v)          { return v; }
__device__ __forceinline__ float to_f32(__nv_bfloat16 v)  { return __bfloat162float(v); }

__device__ __forceinline__ uint32_t pack2(float a, float b) {
    __nv_bfloat162 t = __floats2bfloat162_rn(a, b);
    return *(uint32_t*)&t;
}

// ---------------- PTX wrappers --------------------------------------------------
__device__ __forceinline__ void cp_async16(uint32_t smem, const void* gmem) {
    asm volatile("cp.async.cg.shared.global [%0],[%1],16;\n" :: "r"(smem), "l"(gmem));
}
__device__ __forceinline__ void cp_commit() {
    asm volatile("cp.async.commit_group;\n" ::: "memory");
}
__device__ __forceinline__ void cp_wait0() {
    asm volatile("cp.async.wait_group 0;\n" ::: "memory");
}
__device__ __forceinline__ void cp_wait1() {
    asm volatile("cp.async.wait_group 1;\n" ::: "memory");
}
__device__ __forceinline__ void bar_sync(int id) {
    asm volatile("bar.sync %0, 128;\n" :: "r"(id) : "memory");
}
__device__ __forceinline__ void ldsm_x4(uint32_t& r0, uint32_t& r1, uint32_t& r2, uint32_t& r3,
                                        uint32_t addr) {
    asm volatile("ldmatrix.sync.aligned.m8n8.x4.shared.b16 {%0,%1,%2,%3},[%4];\n"
                 : "=r"(r0), "=r"(r1), "=r"(r2), "=r"(r3) : "r"(addr));
}
__device__ __forceinline__ void ldsm_x4_t(uint32_t& r0, uint32_t& r1, uint32_t& r2, uint32_t& r3,
                                          uint32_t addr) {
    asm volatile("ldmatrix.sync.aligned.m8n8.x4.trans.shared.b16 {%0,%1,%2,%3},[%4];\n"
                 : "=r"(r0), "=r"(r1), "=r"(r2), "=r"(r3) : "r"(addr));
}
__device__ __forceinline__ void mma16816(float* d, const uint32_t* a, uint32_t b0, uint32_t b1) {
    asm volatile("mma.sync.aligned.m16n8k16.row.col.f32.bf16.bf16.f32 "
                 "{%0,%1,%2,%3},{%4,%5,%6,%7},{%8,%9},{%0,%1,%2,%3};\n"
                 : "+f"(d[0]), "+f"(d[1]), "+f"(d[2]), "+f"(d[3])
                 : "r"(a[0]), "r"(a[1]), "r"(a[2]), "r"(a[3]), "r"(b0), "r"(b1));
}

// ---------------- merged weight convert + colnorm partials + rope table ---------
__device__ __forceinline__ void wtile(const float* __restrict__ W,
                                      __nv_bfloat16* __restrict__ Wb,
                                      float* __restrict__ part, float* cred,
                                      int N, int k0, int n0)
{
    int tid = threadIdx.x;
    int n  = n0 + (tid & 63);
    int ks = tid >> 6;
    float s = 0.f;
    #pragma unroll 4
    for (int k = k0 + ks*16; k < k0 + ks*16 + 16; k++) {
        float v = W[(size_t)k * N + n];
        Wb[(size_t)k * N + n] = __float2bfloat16(v);
        s += v * v;
    }
    cred[tid] = s;
    __syncthreads();
    if (tid < 64)
        part[((size_t)(k0 >> 6)) * N + n0 + tid] =
            cred[tid] + cred[tid+64] + cred[tid+128] + cred[tid+192];
}

// tiles: qkv 432 | ao 144 | fcg 1152 | proj 576 | rope 256 => 2560 blocks
__global__ __launch_bounds__(256)
void wconv_all(const float* __restrict__ w_qkv, const float* __restrict__ w_ao,
               const float* __restrict__ w_fc,  const float* __restrict__ w_gate,
               const float* __restrict__ w_proj,
               __nv_bfloat16* __restrict__ wq, __nv_bfloat16* __restrict__ wao,
               __nv_bfloat16* __restrict__ wfcg, __nv_bfloat16* __restrict__ wp,
               float* __restrict__ part, float* __restrict__ rope)
{
    __shared__ float s_cred[256];
    int bid = blockIdx.x;
    if (bid < 432) {            // qkv: K=768(12 kt), N=2304(36 nt)
        int nt = bid % 36, kt = bid / 36;
        wtile(w_qkv, wq, part + PART_QKV, s_cred, 3*Cc, kt*64, nt*64);
    } else if (bid < 576) {     // ao: 12x12
        int l = bid - 432; int nt = l % 12, kt = l / 12;
        wtile(w_ao, wao, part + PART_AO, s_cred, Cc, kt*64, nt*64);
    } else if (bid < 1728) {    // fcg: K=768(12 kt), N=6144(96 nt) interleaved
        int l = bid - 576; int nt = l % 96, kt = l / 96;
        int n0 = nt*64, k0 = kt*64;
        int tid = threadIdx.x;
        int c = n0 + (tid & 63);
        const float* src = (c & 1) ? w_gate : w_fc;
        int j = c >> 1;
        int ks = tid >> 6;
        float s = 0.f;
        #pragma unroll 4
        for (int k = k0 + ks*16; k < k0 + ks*16 + 16; k++) {
            float v = src[(size_t)k * HID + j];
            wfcg[(size_t)k * NFCG + c] = __float2bfloat16(v);
            s += v * v;
        }
        s_cred[tid] = s;
        __syncthreads();
        if (tid < 64)
            part[PART_FCG + ((size_t)(k0 >> 6)) * NFCG + n0 + tid] =
                s_cred[tid] + s_cred[tid+64] + s_cred[tid+128] + s_cred[tid+192];
    } else if (bid < 2304) {    // proj: K=3072(48), N=768(12)
        int l = bid - 1728; int nt = l % 12, kt = l / 12;
        wtile(w_proj, wp, part + PART_PROJ, s_cred, Cc, kt*64, nt*64);
    } else {                    // rope table
        int i = (bid - 2304) * 256 + threadIdx.x;
        int t = i >> 6, d = i & 63, ii = d & 31;
        float fr  = expf(-(float)(2*ii) * (logf(10000.0f) / 64.0f));
        float ang = (float)t * fr;
        rope[i] = (d < 32) ? cosf(ang) : sinf(ang);
    }
}

// ---------------- LayerNorm -> bf16 h, fp32 rownorm -----------------------------
__global__ __launch_bounds__(256)
void ln_kernel(const float* __restrict__ x, const float* __restrict__ sc,
               __nv_bfloat16* __restrict__ h, float* __restrict__ rn)
{
    int row = blockIdx.x;
    const float* xr = x + (size_t)row * Cc;
    int t = threadIdx.x;
    float v0 = xr[t], v1 = xr[t+256], v2 = xr[t+512];
    float s  = v0+v1+v2;
    float ss = v0*v0+v1*v1+v2*v2;
    blockReduceSum2(s, ss);
    float mu  = s  * (1.0f/768.0f);
    float var = ss * (1.0f/768.0f) - mu*mu;
    float rs  = rsqrtf(var + 1e-6f);
    float o0 = (v0-mu)*rs*sc[t];
    float o1 = (v1-mu)*rs*sc[t+256];
    float o2 = (v2-mu)*rs*sc[t+512];
    __nv_bfloat16* hr = h + (size_t)row * Cc;
    hr[t] = __float2bfloat16(o0);
    hr[t+256] = __float2bfloat16(o1);
    hr[t+512] = __float2bfloat16(o2);
    float hn = blockReduceSum(o0*o0+o1*o1+o2*o2);
    if (t == 0) rn[row] = hn;
}

// ---------------- bf16 tensor-core GEMM (4 warps, 64x64 warp tiles) -------------
// MODE 0: yat   MODE 1: extra + yat (in-kernel A rownorm)
// MODE 3: qkv rope (extra=rope table, q scaled 1/8)
// MODE 4: interleaved fc/gate -> u = gelu(yat_gate)*yat_fc, logical N=3072
#define GLDA 40
#define GLDB 136
#define GSTAGES 3

template<int MODE, typename OutT, typename ExtraT>
__global__ __launch_bounds__(128)
void gemm_yat_mma(const __nv_bfloat16* __restrict__ A, const __nv_bfloat16* __restrict__ W,
                  OutT* __restrict__ out,
                  const float* __restrict__ rn, const float* __restrict__ part, int nch,
                  const float* __restrict__ bias, const float* __restrict__ alphap,
                  const float* __restrict__ bias2, const float* __restrict__ alphap2,
                  const ExtraT* __restrict__ extra,
                  int M, int N, int K)
{
    extern __shared__ __nv_bfloat16 smem[];
    __nv_bfloat16* As = smem;                         // GSTAGES * 128*GLDA
    __nv_bfloat16* Bs = smem + GSTAGES*128*GLDA;      // GSTAGES * 32*GLDB
    __shared__ float cns[128];
    __shared__ float rns[128];

    const int tid = threadIdx.x;
    const int m0 = blockIdx.y * 128, n0 = blockIdx.x * 128;

    // A: thread t owns row t (32 elems = 4x16B); B: row = t>>2, 32-col group (t&3)
    const int b_row = tid >> 2, b_col = (tid & 3) * 32;
    const char* Ag = (const char*)(A + (size_t)(m0 + tid) * K);
    const char* Bg = (const char*)(W + (size_t)b_row * N + n0 + b_col);
    const uint32_t As0 = (uint32_t)__cvta_generic_to_shared(As);
    const uint32_t Bs0 = (uint32_t)__cvta_generic_to_shared(Bs);
    const uint32_t Asw = As0 + (uint32_t)(tid*GLDA)*2u;
    const uint32_t Bsw = Bs0 + (uint32_t)(b_row*GLDB + b_col)*2u;
    const uint32_t AS_STG = 128u*GLDA*2u, BS_STG = 32u*GLDB*2u;

    const int lane = tid & 31, warp = tid >> 5;
    const int wm = (warp >> 1) * 64;
    const int wn = (warp & 1) * 64;

    const int KT = K >> 5;

    auto issueT = [&](int kt, int stg) {
        const char* ag = Ag + (size_t)kt * 64;            // 32 bf16 per k-step
        const char* bg = Bg + (size_t)kt * 32 * N * 2;
        uint32_t asd = Asw + (uint32_t)stg * AS_STG;
        uint32_t bsd = Bsw + (uint32_t)stg * BS_STG;
        #pragma unroll
        for (int j = 0; j < 4; j++) {
            cp_async16(asd + j*16u, ag + j*16);
            cp_async16(bsd + j*16u, bg + j*16);
        }
        cp_commit();
    };

    issueT(0, 0); issueT(1, 1);

    // column-norm slice reduce (overlaps cp.async): one col per thread
    {
        float s = 0.f;
        for (int c = 0; c < nch; c++)
            s += part[(size_t)c * N + n0 + tid];
        cns[tid] = s;
    }

    float acc[4][8][4];
    #pragma unroll
    for (int i = 0; i < 4; i++)
        #pragma unroll
        for (int j = 0; j < 8; j++)
            #pragma unroll
            for (int e = 0; e < 4; e++) acc[i][j][e] = 0.f;

    const uint32_t a_mat = As0 + (uint32_t)(((wm + (lane & 15)) * GLDA) + (lane >> 4) * 8)*2u;
    const uint32_t b_mat = Bs0 + (uint32_t)(((lane & 15) * GLDB) + wn + (lane >> 4) * 8)*2u;

    float arn = 0.f;   // MODE 1: row tid's norm (this thread loads the whole row)

    int stg = 0, nstg = 2;
    for (int kt = 0; kt < KT; kt++) {
        if (kt + 1 < KT) cp_wait1(); else cp_wait0();
        __syncthreads();
        if (kt + 2 < KT) {
            issueT(kt + 2, nstg);
            nstg = (nstg == GSTAGES-1) ? 0 : nstg + 1;
        }

        if constexpr (MODE == 1) {
            const __nv_bfloat16* ap = As + (size_t)stg*128*GLDA + tid*GLDA;
            #pragma unroll
            for (int i = 0; i < 16; i++) {
                __nv_bfloat162 v2 = *(const __nv_bfloat162*)(ap + 2*i);
                float f0 = __bfloat162float(v2.x), f1 = __bfloat162float(v2.y);
                arn = fmaf(f0, f0, fmaf(f1, f1, arn));
            }
        }

        uint32_t abase = a_mat + (uint32_t)stg * AS_STG;
        uint32_t bbase = b_mat + (uint32_t)stg * BS_STG;
        stg = (stg == GSTAGES-1) ? 0 : stg + 1;
        #pragma unroll
        for (int kk = 0; kk < 2; kk++) {
            uint32_t ra[4][4];
            uint32_t rb[4][4];
            #pragma unroll
            for (int mt = 0; mt < 4; mt++)
                ldsm_x4(ra[mt][0], ra[mt][1], ra[mt][2], ra[mt][3],
                        abase + (uint32_t)(mt*16*GLDA + kk*16)*2u);
            #pragma unroll
            for (int p = 0; p < 4; p++)
                ldsm_x4_t(rb[p][0], rb[p][1], rb[p][2], rb[p][3],
                          bbase + (uint32_t)(kk*16*GLDB + p*16)*2u);
            #pragma unroll
            for (int mt = 0; mt < 4; mt++)
                #pragma unroll
                for (int nt = 0; nt < 8; nt++)
                    mma16816(acc[mt][nt], ra[mt],
                             rb[nt>>1][(nt&1)*2], rb[nt>>1][(nt&1)*2 + 1]);
        }
    }

    if constexpr (MODE == 1) rns[tid] = arn;
    __syncthreads();

    // --- yat epilogue (fp32) ---
    float scN = (MODE == 4) ? 3072.f : (float)N;
    float sc  = powf(sqrtf(scN) / log1pf(scN), alphap[0]);
    float sc2 = 0.f;
    if constexpr (MODE == 4) sc2 = powf(sqrtf(3072.f) / log1pf(3072.f), alphap2[0]);

    #pragma unroll
    for (int mt = 0; mt < 4; mt++) {
        #pragma unroll
        for (int half = 0; half < 2; half++) {
            int mloc = wm + mt*16 + (lane >> 2) + half*8;
            int m = m0 + mloc;
            float rnv;
            if constexpr (MODE == 1) rnv = rns[mloc];
            else                     rnv = rn[m];
            #pragma unroll
            for (int nt = 0; nt < 8; nt++) {
                int nloc = wn + nt*8 + (lane & 3)*2;
                int n = n0 + nloc;
                float y0 = acc[mt][nt][half*2 + 0];
                float y1 = acc[mt][nt][half*2 + 1];
                float d0 = rnv + cns[nloc]   - 2.0f*y0 + 1e-6f;
                float d1 = rnv + cns[nloc+1] - 2.0f*y1 + 1e-6f;
                if constexpr (MODE == 4) {
                    int j = n >> 1;
                    float vfc = (y0*y0/d0 + bias[j])  * sc;
                    float vgt = (y1*y1/d1 + bias2[j]) * sc2;
                    ((__nv_bfloat16*)out)[(size_t)m*HID + j] =
                        __float2bfloat16(gelu_tanh(vgt) * vfc);
                } else {
                    float v0 = (y0*y0/d0 + bias[n])   * sc;
                    float v1 = (y1*y1/d1 + bias[n+1]) * sc;
                    if constexpr (MODE == 1) {
                        const ExtraT* ep = extra + (size_t)m*N + n;
                        v0 += to_f32(ep[0]); v1 += to_f32(ep[1]);
                    }
                    if constexpr (MODE == 3) {
                        if (n < 2*Cc) {
                            int t  = m % Tt;
                            int dd = n & 63;
                            float f0 = extra[t*64 + dd], f1 = extra[t*64 + dd + 1];
                            if (n < Cc) { f0 *= 0.125f; f1 *= 0.125f; }
                            v0 *= f0; v1 *= f1;
                        }
                    }
                    OutT* op = out + (size_t)m*N + n;
                    if constexpr (sizeof(OutT) == 2) {
                        *(__nv_bfloat162*)op = __floats2bfloat162_rn(v0, v1);
                    } else {
                        *(float2*)op = make_float2(v0, v1);
                    }
                }
            }
        }
    }
}

// ---------------- bf16 mma flash attention: 2-group split-KV, 256 threads -------
#define ALDK 72
__global__ __launch_bounds__(256)
void flash_attn_mma(const __nv_bfloat16* __restrict__ qkv, __nv_bfloat16* __restrict__ o)
{
    __shared__ __nv_bfloat16 KVs[4][64*ALDK];   // group g: K=KVs[2g], V=KVs[2g+1]
    __shared__ float m1s[64], l1s[64];
    float* ovs = (float*)&KVs[2][0];            // merge overlay (group1 buffers), 64x65 f32

    const int tid  = threadIdx.x;
    const int g    = tid >> 7;                  // warp group 0/1
    const int gtid = tid & 127;
    const int lane = tid & 31, warp = tid >> 5;
    const int wg   = warp & 3;
    const int qt = (int)gridDim.x - 1 - (int)blockIdx.x;   // heavy blocks first
    const int h = blockIdx.y, b = blockIdx.z;
    const int t0 = qt * 64;
    const int RS = 3*Cc;
    const int ng = (qt + 2 - g) >> 1;           // tiles for this group

    const int krow = gtid >> 1, koff = (gtid & 1) * 32;
    const __nv_bfloat16* kgbase = qkv + (size_t)(b*Tt + krow) * RS + Cc + h*64 + koff;
    const uint32_t kbL = (uint32_t)__cvta_generic_to_shared(&KVs[2*g][0]);
    const uint32_t vbL = (uint32_t)__cvta_generic_to_shared(&KVs[2*g+1][0]);
    const uint32_t ksw = kbL + (uint32_t)(krow*ALDK + koff)*2u;
    const uint32_t vsw = vbL + (uint32_t)(krow*ALDK + koff)*2u;

    auto issue = [&](int jt) {
        const __nv_bfloat16* kp = kgbase + (size_t)jt * 64 * RS;
        const __nv_bfloat16* vp = kp + Cc;
        #pragma unroll
        for (int i = 0; i < 4; i++) {
            cp_async16(ksw + i*16u, kp + i*8);
            cp_async16(vsw + i*16u, vp + i*8);
        }
        cp_commit();
    };

    if (ng > 0) issue(g);

    uint32_t qa[4][4];
    {
        int r = t0 + wg*16 + (lane >> 2);
        const __nv_bfloat16* q0 = qkv + (size_t)(b*Tt + r) * RS + h*64;
        const __nv_bfloat16* q8 = q0 + (size_t)8 * RS;
        #pragma unroll
        for (int kk = 0; kk < 4; kk++) {
            int c = kk*16 + (lane & 3)*2;
            qa[kk][0] = *(const uint32_t*)(q0 + c);
            qa[kk][1] = *(const uint32_t*)(q8 + c);
            qa[kk][2] = *(const uint32_t*)(q0 + c + 8);
            qa[kk][3] = *(const uint32_t*)(q8 + c + 8);
        }
    }

    float s[8][4], ov[8][4];
    float mrun[2] = {-1e30f, -1e30f}, lrun[2] = {0.f, 0.f};
    #pragma unroll
    for (int nt = 0; nt < 8; nt++)
        #pragma unroll
        for (int e = 0; e < 4; e++) ov[nt][e] = 0.f;

    const uint32_t kofs = (uint32_t)(((lane & 7) + ((lane >> 4) << 3)) * ALDK + (((lane >> 3) & 1) << 3)) * 2u;
    const uint32_t vofs = (uint32_t)((lane & 15) * ALDK + ((lane >> 4) << 3)) * 2u;

    for (int i = 0; i < ng; i++) {
        int jt = g + 2*i;
        cp_wait0();
        bar_sync(1 + g);

        #pragma unroll
        for (int nt = 0; nt < 8; nt++)
            #pragma unroll
            for (int e = 0; e < 4; e++) s[nt][e] = 0.f;
        uint32_t kb = kbL + kofs;
        #pragma unroll
        for (int kk = 0; kk < 4; kk++) {
            #pragma unroll
            for (int p = 0; p < 4; p++) {
                uint32_t r0, r1, r2, r3;
                ldsm_x4(r0, r1, r2, r3, kb + (uint32_t)(p*16*ALDK + kk*16)*2u);
                mma16816(s[2*p],   qa[kk], r0, r1);
                mma16816(s[2*p+1], qa[kk], r2, r3);
            }
        }

        bool diag = (jt == qt);
        #pragma unroll
        for (int half = 0; half < 2; half++) {
            int grow = t0 + wg*16 + (lane >> 2) + half*8;
            float mx = mrun[half];
            #pragma unroll
            for (int nt = 0; nt < 8; nt++) {
                float v0 = s[nt][half*2], v1 = s[nt][half*2+1];
                if (diag) {
                    int c0 = jt*64 + nt*8 + (lane & 3)*2;
                    if (c0     > grow) v0 = -1e30f;
                    if (c0 + 1 > grow) v1 = -1e30f;
                    s[nt][half*2] = v0; s[nt][half*2+1] = v1;
                }
                mx = fmaxf(mx, fmaxf(v0, v1));
            }
            mx = fmaxf(mx, __shfl_xor_sync(0xffffffffu, mx, 1));
            mx = fmaxf(mx, __shfl_xor_sync(0xffffffffu, mx, 2));
            float corr = __expf(mrun[half] - mx);
            mrun[half] = mx;
            float ls = 0.f;
            #pragma unroll
            for (int nt = 0; nt < 8; nt++) {
                float p0 = __expf(s[nt][half*2]   - mx);
                float p1 = __expf(s[nt][half*2+1] - mx);
                s[nt][half*2] = p0; s[nt][half*2+1] = p1;
                ls += p0 + p1;
            }
            ls += __shfl_xor_sync(0xffffffffu, ls, 1);
            ls += __shfl_xor_sync(0xffffffffu, ls, 2);
            lrun[half] = lrun[half]*corr + ls;
            #pragma unroll
            for (int nt = 0; nt < 8; nt++) { ov[nt][half*2] *= corr; ov[nt][half*2+1] *= corr; }
        }

        uint32_t pa[4][4];
        #pragma unroll
        for (int kk = 0; kk < 4; kk++) {
            pa[kk][0] = pack2(s[2*kk][0],   s[2*kk][1]);
            pa[kk][1] = pack2(s[2*kk][2],   s[2*kk][3]);
            pa[kk][2] = pack2(s[2*kk+1][0], s[2*kk+1][1]);
            pa[kk][3] = pack2(s[2*kk+1][2], s[2*kk+1][3]);
        }
        uint32_t vb = vbL + vofs;
        #pragma unroll
        for (int kk = 0; kk < 4; kk++) {
            #pragma unroll
            for (int p = 0; p < 4; p++) {
                uint32_t r0, r1, r2, r3;
                ldsm_x4_t(r0, r1, r2, r3, vb + (uint32_t)(kk*16*ALDK + p*16)*2u);
                mma16816(ov[2*p],   pa[kk], r0, r1);
                mma16816(ov[2*p+1], pa[kk], r2, r3);
            }
        }

        bar_sync(1 + g);
        if (i + 1 < ng) issue(g + 2*(i + 1));
    }

    // ---- merge the two groups ----
    __syncthreads();
    if (g == 1) {
        #pragma unroll
        for (int half = 0; half < 2; half++) {
            int rloc = wg*16 + (lane >> 2) + half*8;
            if ((lane & 3) == 0) { m1s[rloc] = mrun[half]; l1s[rloc] = lrun[half]; }
            #pragma unroll
            for (int nt = 0; nt < 8; nt++) {
                int c = nt*8 + (lane & 3)*2;
                ovs[rloc*65 + c]     = ov[nt][half*2];
                ovs[rloc*65 + c + 1] = ov[nt][half*2+1];
            }
        }
    }
    __syncthreads();
    if (g == 0) {
        #pragma unroll
        for (int half = 0; half < 2; half++) {
            int rloc = wg*16 + (lane >> 2) + half*8;
            float m1 = m1s[rloc], l1 = l1s[rloc];
            float ms = fmaxf(mrun[half], m1);
            float c0 = __expf(mrun[half] - ms);
            float c1 = __expf(m1 - ms);
            float inv = 1.0f / (lrun[half]*c0 + l1*c1);
            __nv_bfloat16* op = o + (size_t)(b*Tt + t0 + rloc)*Cc + h*64;
            #pragma unroll
            for (int nt = 0; nt < 8; nt++) {
                int c = nt*8 + (lane & 3)*2;
                float o0 = (ov[nt][half*2]  *c0 + ovs[rloc*65 + c]    *c1) * inv;
                float o1 = (ov[nt][half*2+1]*c0 + ovs[rloc*65 + c + 1]*c1) * inv;
                *(__nv_bfloat162*)(op + c) = __floats2bfloat162_rn(o0, o1);
            }
        }
    }
}

// ---------------- launch --------------------------------------------------------
extern "C" void kernel_launch(void* const* d_in, const int* in_sizes, int n_in,
                              void* d_out, int out_size)
{
    (void)in_sizes; (void)n_in; (void)out_size;
    const float* x      = (const float*)d_in[0];
    const float* ln1    = (const float*)d_in[2];
    const float* w_qkv  = (const float*)d_in[3];
    const float* b_qkv  = (const float*)d_in[4];
    const float* a_qkv  = (const float*)d_in[5];
    const float* w_ao   = (const float*)d_in[6];
    const float* b_ao   = (const float*)d_in[7];
    const float* a_ao   = (const float*)d_in[8];
    const float* ln2    = (const float*)d_in[9];
    const float* w_fc   = (const float*)d_in[10];
    const float* b_fc   = (const float*)d_in[11];
    const float* a_fc   = (const float*)d_in[12];
    const float* w_gate = (const float*)d_in[13];
    const float* b_gate = (const float*)d_in[14];
    const float* a_gate = (const float*)d_in[15];
    const float* w_proj = (const float*)d_in[16];
    const float* b_proj = (const float*)d_in[17];
    const float* a_proj = (const float*)d_in[18];
    float* out = (float*)d_out;

    float *x1, *rn, *part, *ropetab;
    __nv_bfloat16 *qkvb, *h, *o, *h2, *u, *wq, *wao, *wfcg, *wp;
    cudaGetSymbolAddress((void**)&x1,     g_x1);
    cudaGetSymbolAddress((void**)&rn,     g_rn);
    cudaGetSymbolAddress((void**)&part,   g_part);
    cudaGetSymbolAddress((void**)&ropetab,g_rope);
    cudaGetSymbolAddress((void**)&qkvb,   g_qkvb);
    cudaGetSymbolAddress((void**)&h,      g_h);
    cudaGetSymbolAddress((void**)&o,      g_o);
    cudaGetSymbolAddress((void**)&h2,     g_h2);
    cudaGetSymbolAddress((void**)&u,      g_u);
    cudaGetSymbolAddress((void**)&wq,     g_wq);
    cudaGetSymbolAddress((void**)&wao,    g_wao);
    cudaGetSymbolAddress((void**)&wfcg,   g_wfcg);
    cudaGetSymbolAddress((void**)&wp,     g_wp);

    const int GSMEM = GSTAGES * (128*GLDA + 32*GLDB) * (int)sizeof(__nv_bfloat16);
    cudaFuncSetAttribute(gemm_yat_mma<1, float, float>,
                         cudaFuncAttributeMaxDynamicSharedMemorySize, GSMEM);
    cudaFuncSetAttribute(gemm_yat_mma<3, __nv_bfloat16, float>,
                         cudaFuncAttributeMaxDynamicSharedMemorySize, GSMEM);
    cudaFuncSetAttribute(gemm_yat_mma<4, __nv_bfloat16, float>,
                         cudaFuncAttributeMaxDynamicSharedMemorySize, GSMEM);

    // 0. all weight conversions + colnorm partials + rope table (one launch)
    wconv_all<<<2560, 256>>>(w_qkv, w_ao, w_fc, w_gate, w_proj,
                             wq, wao, wfcg, wp, part, ropetab);

    // 1. LN1 -> h (bf16), rn
    ln_kernel<<<Mrows, 256>>>(x, ln1, h, rn);

    // 2. qkv = rope(yat(h @ w_qkv)) bf16, q pre-scaled by 1/8
    gemm_yat_mma<3, __nv_bfloat16, float><<<dim3(3*Cc/128, Mrows/128), 128, GSMEM>>>(
        h, wq, qkvb, rn, part + PART_QKV, Cc/64, b_qkv, a_qkv, nullptr, nullptr,
        ropetab, Mrows, 3*Cc, Cc);

    // 3. attention -> o (bf16)
    flash_attn_mma<<<dim3(Tt/64, Hh, Bb), 256>>>(qkvb, o);

    // 4. x1 = x + yat(o @ w_ao)
    gemm_yat_mma<1, float, float><<<dim3(Cc/128, Mrows/128), 128, GSMEM>>>(
        o, wao, x1, rn, part + PART_AO, Cc/64, b_ao, a_ao, nullptr, nullptr,
        x, Mrows, Cc, Cc);

    // 5. LN2 -> h2 (bf16), rn
    ln_kernel<<<Mrows, 256>>>(x1, ln2, h2, rn);

    // 6+7. u = gelu(yat(h2@w_gate)) * yat(h2@w_fc)  (one interleaved GEMM)
    gemm_yat_mma<4, __nv_bfloat16, float><<<dim3(NFCG/128, Mrows/128), 128, GSMEM>>>(
        h2, wfcg, u, rn, part + PART_FCG, Cc/64, b_fc, a_fc, b_gate, a_gate,
        (const float*)nullptr, Mrows, NFCG, Cc);

    // 8. out = x1 + yat(u @ w_proj)
    gemm_yat_mma<1, float, float><<<dim3(Cc/128, Mrows/128), 128, GSMEM>>>(
        u, wp, out, rn, part + PART_PROJ, HID/64, b_proj, a_proj, nullptr, nullptr,
        x1, Mrows, Cc, HID);
}

// round 15
// speedup vs baseline: 1.1777x; 1.1777x over previous
#include <cstdint>
#include <cstddef>
#include <cuda_runtime.h>
#include <cuda_bf16.h>
#include <math.h>

#define Bb   2
#define Tt   1024
#define Cc   768
#define Hh   12
#define HID  3072
#define NFCG 6144
#define Mrows (Bb*Tt)          // 2048

// part region offsets (floats)
#define PART_QKV  0            // 12*2304
#define PART_AO   27648        // 12*768
#define PART_FCG  36864        // 12*6144
#define PART_PROJ 110592       // 48*768
#define PART_TOT  147456

// ---------------- scratch (static device arrays; no cudaMalloc) ----------------
__device__ float g_x1  [Mrows*Cc];
__device__ float g_rn  [Mrows];
__device__ float g_part[PART_TOT];
__device__ float g_rope[Tt*64];
__device__ __nv_bfloat16 g_qkvb[Mrows*3*Cc];
__device__ __nv_bfloat16 g_h   [Mrows*Cc];
__device__ __nv_bfloat16 g_o   [Mrows*Cc];
__device__ __nv_bfloat16 g_h2  [Mrows*Cc];
__device__ __nv_bfloat16 g_u   [Mrows*HID];
__device__ __nv_bfloat16 g_wq  [Cc*3*Cc];
__device__ __nv_bfloat16 g_wao [Cc*Cc];
__device__ __nv_bfloat16 g_wfcg[Cc*NFCG];      // interleaved: col 2j=fc_j, 2j+1=gate_j
__device__ __nv_bfloat16 g_wp  [HID*Cc];

// ---------------- helpers ------------------------------------------------------
__device__ __forceinline__ float blockReduceSum(float v) {
    __shared__ float sh[8];
    int lane = threadIdx.x & 31, w = threadIdx.x >> 5;
    #pragma unroll
    for (int o = 16; o; o >>= 1) v += __shfl_xor_sync(0xffffffffu, v, o);
    __syncthreads();
    if (lane == 0) sh[w] = v;
    __syncthreads();
    return sh[0]+sh[1]+sh[2]+sh[3]+sh[4]+sh[5]+sh[6]+sh[7];
}

__device__ __forceinline__ void blockReduceSum2(float& a, float& b) {
    __shared__ float sha[8], shb[8];
    int lane = threadIdx.x & 31, w = threadIdx.x >> 5;
    #pragma unroll
    for (int o = 16; o; o >>= 1) {
        a += __shfl_xor_sync(0xffffffffu, a, o);
        b += __shfl_xor_sync(0xffffffffu, b, o);
    }
    __syncthreads();
    if (lane == 0) { sha[w] = a; shb[w] = b; }
    __syncthreads();
    a = sha[0]+sha[1]+sha[2]+sha[3]+sha[4]+sha[5]+sha[6]+sha[7];
    b = shb[0]+shb[1]+shb[2]+shb[3]+shb[4]+shb[5]+shb[6]+shb[7];
}

__device__ __forceinline__ float gelu_tanh(float x) {
    float x3 = x * x * x;
    float t  = tanhf(0.7978845608028654f * (x + 0.044715f * x3));
    return 0.5f * x * (1.0f + t);
}

__device__ __forceinline__ float to_f32(float v)          { return v; }
__device__ __forceinline__ float to_f32(__nv_bfloat16 v)  { return __bfloat162float(v); }

__device__ __forceinline__ uint32_t pack2(float a, float b) {
    __nv_bfloat162 t = __floats2bfloat162_rn(a, b);
    return *(uint32_t*)&t;
}

// ---------------- PTX wrappers --------------------------------------------------
__device__ __forceinline__ void cp_async16(uint32_t smem, const void* gmem) {
    asm volatile("cp.async.cg.shared.global [%0],[%1],16;\n" :: "r"(smem), "l"(gmem));
}
__device__ __forceinline__ void cp_commit() {
    asm volatile("cp.async.commit_group;\n" ::: "memory");
}
__device__ __forceinline__ void cp_wait0() {
    asm volatile("cp.async.wait_group 0;\n" ::: "memory");
}
__device__ __forceinline__ void cp_wait1() {
    asm volatile("cp.async.wait_group 1;\n" ::: "memory");
}
__device__ __forceinline__ void bar_sync(int id) {
    asm volatile("bar.sync %0, 128;\n" :: "r"(id) : "memory");
}
__device__ __forceinline__ void ldsm_x4(uint32_t& r0, uint32_t& r1, uint32_t& r2, uint32_t& r3,
                                        uint32_t addr) {
    asm volatile("ldmatrix.sync.aligned.m8n8.x4.shared.b16 {%0,%1,%2,%3},[%4];\n"
                 : "=r"(r0), "=r"(r1), "=r"(r2), "=r"(r3) : "r"(addr));
}
__device__ __forceinline__ void ldsm_x4_t(uint32_t& r0, uint32_t& r1, uint32_t& r2, uint32_t& r3,
                                          uint32_t addr) {
    asm volatile("ldmatrix.sync.aligned.m8n8.x4.trans.shared.b16 {%0,%1,%2,%3},[%4];\n"
                 : "=r"(r0), "=r"(r1), "=r"(r2), "=r"(r3) : "r"(addr));
}
__device__ __forceinline__ void mma16816(float* d, const uint32_t* a, uint32_t b0, uint32_t b1) {
    asm volatile("mma.sync.aligned.m16n8k16.row.col.f32.bf16.bf16.f32 "
                 "{%0,%1,%2,%3},{%4,%5,%6,%7},{%8,%9},{%0,%1,%2,%3};\n"
                 : "+f"(d[0]), "+f"(d[1]), "+f"(d[2]), "+f"(d[3])
                 : "r"(a[0]), "r"(a[1]), "r"(a[2]), "r"(a[3]), "r"(b0), "r"(b1));
}

// ---------------- merged weight convert + colnorm partials + rope table ---------
__device__ __forceinline__ void wtile(const float* __restrict__ W,
                                      __nv_bfloat16* __restrict__ Wb,
                                      float* __restrict__ part, float* cred,
                                      int N, int k0, int n0)
{
    int tid = threadIdx.x;
    int n  = n0 + (tid & 63);
    int ks = tid >> 6;
    float s = 0.f;
    #pragma unroll 4
    for (int k = k0 + ks*16; k < k0 + ks*16 + 16; k++) {
        float v = W[(size_t)k * N + n];
        Wb[(size_t)k * N + n] = __float2bfloat16(v);
        s += v * v;
    }
    cred[tid] = s;
    __syncthreads();
    if (tid < 64)
        part[((size_t)(k0 >> 6)) * N + n0 + tid] =
            cred[tid] + cred[tid+64] + cred[tid+128] + cred[tid+192];
}

// tiles: qkv 432 | ao 144 | fcg 1152 | proj 576 | rope 256 => 2560 blocks
__global__ __launch_bounds__(256)
void wconv_all(const float* __restrict__ w_qkv, const float* __restrict__ w_ao,
               const float* __restrict__ w_fc,  const float* __restrict__ w_gate,
               const float* __restrict__ w_proj,
               __nv_bfloat16* __restrict__ wq, __nv_bfloat16* __restrict__ wao,
               __nv_bfloat16* __restrict__ wfcg, __nv_bfloat16* __restrict__ wp,
               float* __restrict__ part, float* __restrict__ rope)
{
    __shared__ float s_cred[256];
    int bid = blockIdx.x;
    if (bid < 432) {            // qkv: K=768(12 kt), N=2304(36 nt)
        int nt = bid % 36, kt = bid / 36;
        wtile(w_qkv, wq, part + PART_QKV, s_cred, 3*Cc, kt*64, nt*64);
    } else if (bid < 576) {     // ao: 12x12
        int l = bid - 432; int nt = l % 12, kt = l / 12;
        wtile(w_ao, wao, part + PART_AO, s_cred, Cc, kt*64, nt*64);
    } else if (bid < 1728) {    // fcg: K=768(12 kt), N=6144(96 nt) interleaved
        int l = bid - 576; int nt = l % 96, kt = l / 96;
        int n0 = nt*64, k0 = kt*64;
        int tid = threadIdx.x;
        int c = n0 + (tid & 63);
        const float* src = (c & 1) ? w_gate : w_fc;
        int j = c >> 1;
        int ks = tid >> 6;
        float s = 0.f;
        #pragma unroll 4
        for (int k = k0 + ks*16; k < k0 + ks*16 + 16; k++) {
            float v = src[(size_t)k * HID + j];
            wfcg[(size_t)k * NFCG + c] = __float2bfloat16(v);
            s += v * v;
        }
        s_cred[tid] = s;
        __syncthreads();
        if (tid < 64)
            part[PART_FCG + ((size_t)(k0 >> 6)) * NFCG + n0 + tid] =
                s_cred[tid] + s_cred[tid+64] + s_cred[tid+128] + s_cred[tid+192];
    } else if (bid < 2304) {    // proj: K=3072(48), N=768(12)
        int l = bid - 1728; int nt = l % 12, kt = l / 12;
        wtile(w_proj, wp, part + PART_PROJ, s_cred, Cc, kt*64, nt*64);
    } else {                    // rope table
        int i = (bid - 2304) * 256 + threadIdx.x;
        int t = i >> 6, d = i & 63, ii = d & 31;
        float fr  = expf(-(float)(2*ii) * (logf(10000.0f) / 64.0f));
        float ang = (float)t * fr;
        rope[i] = (d < 32) ? cosf(ang) : sinf(ang);
    }
}

// ---------------- LayerNorm -> bf16 h, fp32 rownorm -----------------------------
__global__ __launch_bounds__(256)
void ln_kernel(const float* __restrict__ x, const float* __restrict__ sc,
               __nv_bfloat16* __restrict__ h, float* __restrict__ rn)
{
    int row = blockIdx.x;
    const float* xr = x + (size_t)row * Cc;
    int t = threadIdx.x;
    float v0 = xr[t], v1 = xr[t+256], v2 = xr[t+512];
    float s  = v0+v1+v2;
    float ss = v0*v0+v1*v1+v2*v2;
    blockReduceSum2(s, ss);
    float mu  = s  * (1.0f/768.0f);
    float var = ss * (1.0f/768.0f) - mu*mu;
    float rs  = rsqrtf(var + 1e-6f);
    float o0 = (v0-mu)*rs*sc[t];
    float o1 = (v1-mu)*rs*sc[t+256];
    float o2 = (v2-mu)*rs*sc[t+512];
    __nv_bfloat16* hr = h + (size_t)row * Cc;
    hr[t] = __float2bfloat16(o0);
    hr[t+256] = __float2bfloat16(o1);
    hr[t+512] = __float2bfloat16(o2);
    float hn = blockReduceSum(o0*o0+o1*o1+o2*o2);
    if (t == 0) rn[row] = hn;
}

// ---------------- bf16 tensor-core GEMM (8 warps, 64x32 warp tiles, BK=64) ------
// MODE 0: yat   MODE 1: extra + yat (in-kernel A rownorm)
// MODE 3: qkv rope (extra=rope table, q scaled 1/8)
// MODE 4: interleaved fc/gate -> u = gelu(yat_gate)*yat_fc, logical N=3072
#define GLDA 72     // 64 + 8 pad (bf16 elems)
#define GLDB 136    // 128 + 8 pad
#define GSTAGES 3

template<int MODE, typename OutT, typename ExtraT>
__global__ __launch_bounds__(256, 2)
void gemm_yat_mma(const __nv_bfloat16* __restrict__ A, const __nv_bfloat16* __restrict__ W,
                  OutT* __restrict__ out,
                  const float* __restrict__ rn, const float* __restrict__ part, int nch,
                  const float* __restrict__ bias, const float* __restrict__ alphap,
                  const float* __restrict__ bias2, const float* __restrict__ alphap2,
                  const ExtraT* __restrict__ extra,
                  int M, int N, int K)
{
    extern __shared__ __nv_bfloat16 smem[];
    __nv_bfloat16* As = smem;                         // GSTAGES * 128*GLDA
    __nv_bfloat16* Bs = smem + GSTAGES*128*GLDA;      // GSTAGES * 64*GLDB
    __shared__ float cns[128];
    __shared__ float cred[256];
    __shared__ float rns[128];

    const int tid = threadIdx.x;
    const int m0 = blockIdx.y * 128, n0 = blockIdx.x * 128;

    // A tile 128x64: row = tid>>1, 32-elem half (tid&1); B tile 64x128: row=tid>>2, 32-col qtr
    const int a_row = tid >> 1, a_col = (tid & 1) * 32;
    const int b_row = tid >> 2, b_col = (tid & 3) * 32;
    const char* Ag = (const char*)(A + (size_t)(m0 + a_row) * K + a_col);
    const char* Bg = (const char*)(W + (size_t)b_row * N + n0 + b_col);
    const uint32_t As0 = (uint32_t)__cvta_generic_to_shared(As);
    const uint32_t Bs0 = (uint32_t)__cvta_generic_to_shared(Bs);
    const uint32_t Asw = As0 + (uint32_t)(a_row*GLDA + a_col)*2u;
    const uint32_t Bsw = Bs0 + (uint32_t)(b_row*GLDB + b_col)*2u;
    const uint32_t AS_STG = 128u*GLDA*2u, BS_STG = 64u*GLDB*2u;

    const int lane = tid & 31, warp = tid >> 5;
    const int wm = (warp >> 2) * 64;
    const int wn = (warp & 3) * 32;

    const int KT = K >> 6;     // BK = 64

    auto issueT = [&](int kt, int stg) {
        const char* ag = Ag + (size_t)kt * 128;           // 64 bf16 per k-step
        const char* bg = Bg + (size_t)kt * 64 * N * 2;
        uint32_t asd = Asw + (uint32_t)stg * AS_STG;
        uint32_t bsd = Bsw + (uint32_t)stg * BS_STG;
        #pragma unroll
        for (int j = 0; j < 4; j++) {
            cp_async16(asd + j*16u, ag + j*16);
            cp_async16(bsd + j*16u, bg + j*16);
        }
        cp_commit();
    };

    issueT(0, 0); issueT(1, 1);

    // column-norm slice reduce (overlaps cp.async)
    {
        int col  = tid & 127;
        int half = tid >> 7;
        float s = 0.f;
        for (int c = half; c < nch; c += 2)
            s += part[(size_t)c * N + n0 + col];
        cred[tid] = s;
    }
    __syncthreads();
    if (tid < 128) cns[tid] = cred[tid] + cred[tid + 128];

    float acc[4][4][4];
    #pragma unroll
    for (int i = 0; i < 4; i++)
        #pragma unroll
        for (int j = 0; j < 4; j++)
            #pragma unroll
            for (int e = 0; e < 4; e++) acc[i][j][e] = 0.f;

    const uint32_t a_mat = As0 + (uint32_t)(((wm + (lane & 15)) * GLDA) + (lane >> 4) * 8)*2u;
    const uint32_t b_mat = Bs0 + (uint32_t)(((lane & 15) * GLDB) + wn + (lane >> 4) * 8)*2u;

    float arn = 0.f;   // MODE 1: partial row norm (this thread's 32-elem half-row)

    int stg = 0, nstg = 2;
    for (int kt = 0; kt < KT; kt++) {
        if (kt + 1 < KT) cp_wait1(); else cp_wait0();
        __syncthreads();
        if (kt + 2 < KT) {
            issueT(kt + 2, nstg);
            nstg = (nstg == GSTAGES-1) ? 0 : nstg + 1;
        }

        if constexpr (MODE == 1) {
            const __nv_bfloat16* ap = As + (size_t)stg*128*GLDA + a_row*GLDA + a_col;
            #pragma unroll
            for (int i = 0; i < 16; i++) {
                __nv_bfloat162 v2 = *(const __nv_bfloat162*)(ap + 2*i);
                float f0 = __bfloat162float(v2.x), f1 = __bfloat162float(v2.y);
                arn = fmaf(f0, f0, fmaf(f1, f1, arn));
            }
        }

        uint32_t abase = a_mat + (uint32_t)stg * AS_STG;
        uint32_t bbase = b_mat + (uint32_t)stg * BS_STG;
        stg = (stg == GSTAGES-1) ? 0 : stg + 1;
        #pragma unroll
        for (int kk = 0; kk < 4; kk++) {
            uint32_t ra[4][4];
            uint32_t rb[2][4];
            #pragma unroll
            for (int mt = 0; mt < 4; mt++)
                ldsm_x4(ra[mt][0], ra[mt][1], ra[mt][2], ra[mt][3],
                        abase + (uint32_t)(mt*16*GLDA + kk*16)*2u);
            #pragma unroll
            for (int p = 0; p < 2; p++)
                ldsm_x4_t(rb[p][0], rb[p][1], rb[p][2], rb[p][3],
                          bbase + (uint32_t)(kk*16*GLDB + p*16)*2u);
            #pragma unroll
            for (int mt = 0; mt < 4; mt++)
                #pragma unroll
                for (int nt = 0; nt < 4; nt++)
                    mma16816(acc[mt][nt], ra[mt],
                             rb[nt>>1][(nt&1)*2], rb[nt>>1][(nt&1)*2 + 1]);
        }
    }

    if constexpr (MODE == 1) {
        arn += __shfl_xor_sync(0xffffffffu, arn, 1);   // combine the two half-rows
        if ((tid & 1) == 0) rns[a_row] = arn;
    }
    __syncthreads();

    // --- yat epilogue (fp32) ---
    float scN = (MODE == 4) ? 3072.f : (float)N;
    float sc  = powf(sqrtf(scN) / log1pf(scN), alphap[0]);
    float sc2 = 0.f;
    if constexpr (MODE == 4) sc2 = powf(sqrtf(3072.f) / log1pf(3072.f), alphap2[0]);

    #pragma unroll
    for (int mt = 0; mt < 4; mt++) {
        #pragma unroll
        for (int half = 0; half < 2; half++) {
            int mloc = wm + mt*16 + (lane >> 2) + half*8;
            int m = m0 + mloc;
            float rnv;
            if constexpr (MODE == 1) rnv = rns[mloc];
            else                     rnv = rn[m];
            #pragma unroll
            for (int nt = 0; nt < 4; nt++) {
                int nloc = wn + nt*8 + (lane & 3)*2;
                int n = n0 + nloc;
                float y0 = acc[mt][nt][half*2 + 0];
                float y1 = acc[mt][nt][half*2 + 1];
                float d0 = rnv + cns[nloc]   - 2.0f*y0 + 1e-6f;
                float d1 = rnv + cns[nloc+1] - 2.0f*y1 + 1e-6f;
                if constexpr (MODE == 4) {
                    int j = n >> 1;
                    float vfc = (y0*y0/d0 + bias[j])  * sc;
                    float vgt = (y1*y1/d1 + bias2[j]) * sc2;
                    ((__nv_bfloat16*)out)[(size_t)m*HID + j] =
                        __float2bfloat16(gelu_tanh(vgt) * vfc);
                } else {
                    float v0 = (y0*y0/d0 + bias[n])   * sc;
                    float v1 = (y1*y1/d1 + bias[n+1]) * sc;
                    if constexpr (MODE == 1) {
                        const ExtraT* ep = extra + (size_t)m*N + n;
                        v0 += to_f32(ep[0]); v1 += to_f32(ep[1]);
                    }
                    if constexpr (MODE == 3) {
                        if (n < 2*Cc) {
                            int t  = m % Tt;
                            int dd = n & 63;
                            float f0 = extra[t*64 + dd], f1 = extra[t*64 + dd + 1];
                            if (n < Cc) { f0 *= 0.125f; f1 *= 0.125f; }
                            v0 *= f0; v1 *= f1;
                        }
                    }
                    OutT* op = out + (size_t)m*N + n;
                    if constexpr (sizeof(OutT) == 2) {
                        *(__nv_bfloat162*)op = __floats2bfloat162_rn(v0, v1);
                    } else {
                        *(float2*)op = make_float2(v0, v1);
                    }
                }
            }
        }
    }
}

// ---------------- bf16 mma flash attention: 2-group split-KV, 256 threads -------
#define ALDK 72
__global__ __launch_bounds__(256)
void flash_attn_mma(const __nv_bfloat16* __restrict__ qkv, __nv_bfloat16* __restrict__ o)
{
    __shared__ __nv_bfloat16 KVs[4][64*ALDK];   // group g: K=KVs[2g], V=KVs[2g+1]
    __shared__ float m1s[64], l1s[64];
    float* ovs = (float*)&KVs[2][0];            // merge overlay (group1 buffers), 64x65 f32

    const int tid  = threadIdx.x;
    const int g    = tid >> 7;                  // warp group 0/1
    const int gtid = tid & 127;
    const int lane = tid & 31, warp = tid >> 5;
    const int wg   = warp & 3;
    const int qt = (int)gridDim.x - 1 - (int)blockIdx.x;   // heavy blocks first
    const int h = blockIdx.y, b = blockIdx.z;
    const int t0 = qt * 64;
    const int RS = 3*Cc;
    const int ng = (qt + 2 - g) >> 1;           // tiles for this group

    const int krow = gtid >> 1, koff = (gtid & 1) * 32;
    const __nv_bfloat16* kgbase = qkv + (size_t)(b*Tt + krow) * RS + Cc + h*64 + koff;
    const uint32_t kbL = (uint32_t)__cvta_generic_to_shared(&KVs[2*g][0]);
    const uint32_t vbL = (uint32_t)__cvta_generic_to_shared(&KVs[2*g+1][0]);
    const uint32_t ksw = kbL + (uint32_t)(krow*ALDK + koff)*2u;
    const uint32_t vsw = vbL + (uint32_t)(krow*ALDK + koff)*2u;

    auto issue = [&](int jt) {
        const __nv_bfloat16* kp = kgbase + (size_t)jt * 64 * RS;
        const __nv_bfloat16* vp = kp + Cc;
        #pragma unroll
        for (int i = 0; i < 4; i++) {
            cp_async16(ksw + i*16u, kp + i*8);
            cp_async16(vsw + i*16u, vp + i*8);
        }
        cp_commit();
    };

    if (ng > 0) issue(g);

    uint32_t qa[4][4];
    {
        int r = t0 + wg*16 + (lane >> 2);
        const __nv_bfloat16* q0 = qkv + (size_t)(b*Tt + r) * RS + h*64;
        const __nv_bfloat16* q8 = q0 + (size_t)8 * RS;
        #pragma unroll
        for (int kk = 0; kk < 4; kk++) {
            int c = kk*16 + (lane & 3)*2;
            qa[kk][0] = *(const uint32_t*)(q0 + c);
            qa[kk][1] = *(const uint32_t*)(q8 + c);
            qa[kk][2] = *(const uint32_t*)(q0 + c + 8);
            qa[kk][3] = *(const uint32_t*)(q8 + c + 8);
        }
    }

    float s[8][4], ov[8][4];
    float mrun[2] = {-1e30f, -1e30f}, lrun[2] = {0.f, 0.f};
    #pragma unroll
    for (int nt = 0; nt < 8; nt++)
        #pragma unroll
        for (int e = 0; e < 4; e++) ov[nt][e] = 0.f;

    const uint32_t kofs = (uint32_t)(((lane & 7) + ((lane >> 4) << 3)) * ALDK + (((lane >> 3) & 1) << 3)) * 2u;
    const uint32_t vofs = (uint32_t)((lane & 15) * ALDK + ((lane >> 4) << 3)) * 2u;

    for (int i = 0; i < ng; i++) {
        int jt = g + 2*i;
        cp_wait0();
        bar_sync(1 + g);

        #pragma unroll
        for (int nt = 0; nt < 8; nt++)
            #pragma unroll
            for (int e = 0; e < 4; e++) s[nt][e] = 0.f;
        uint32_t kb = kbL + kofs;
        #pragma unroll
        for (int kk = 0; kk < 4; kk++) {
            #pragma unroll
            for (int p = 0; p < 4; p++) {
                uint32_t r0, r1, r2, r3;
                ldsm_x4(r0, r1, r2, r3, kb + (uint32_t)(p*16*ALDK + kk*16)*2u);
                mma16816(s[2*p],   qa[kk], r0, r1);
                mma16816(s[2*p+1], qa[kk], r2, r3);
            }
        }

        bool diag = (jt == qt);
        #pragma unroll
        for (int half = 0; half < 2; half++) {
            int grow = t0 + wg*16 + (lane >> 2) + half*8;
            float mx = mrun[half];
            #pragma unroll
            for (int nt = 0; nt < 8; nt++) {
                float v0 = s[nt][half*2], v1 = s[nt][half*2+1];
                if (diag) {
                    int c0 = jt*64 + nt*8 + (lane & 3)*2;
                    if (c0     > grow) v0 = -1e30f;
                    if (c0 + 1 > grow) v1 = -1e30f;
                    s[nt][half*2] = v0; s[nt][half*2+1] = v1;
                }
                mx = fmaxf(mx, fmaxf(v0, v1));
            }
            mx = fmaxf(mx, __shfl_xor_sync(0xffffffffu, mx, 1));
            mx = fmaxf(mx, __shfl_xor_sync(0xffffffffu, mx, 2));
            float corr = __expf(mrun[half] - mx);
            mrun[half] = mx;
            float ls = 0.f;
            #pragma unroll
            for (int nt = 0; nt < 8; nt++) {
                float p0 = __expf(s[nt][half*2]   - mx);
                float p1 = __expf(s[nt][half*2+1] - mx);
                s[nt][half*2] = p0; s[nt][half*2+1] = p1;
                ls += p0 + p1;
            }
            ls += __shfl_xor_sync(0xffffffffu, ls, 1);
            ls += __shfl_xor_sync(0xffffffffu, ls, 2);
            lrun[half] = lrun[half]*corr + ls;
            #pragma unroll
            for (int nt = 0; nt < 8; nt++) { ov[nt][half*2] *= corr; ov[nt][half*2+1] *= corr; }
        }

        uint32_t pa[4][4];
        #pragma unroll
        for (int kk = 0; kk < 4; kk++) {
            pa[kk][0] = pack2(s[2*kk][0],   s[2*kk][1]);
            pa[kk][1] = pack2(s[2*kk][2],   s[2*kk][3]);
            pa[kk][2] = pack2(s[2*kk+1][0], s[2*kk+1][1]);
            pa[kk][3] = pack2(s[2*kk+1][2], s[2*kk+1][3]);
        }
        uint32_t vb = vbL + vofs;
        #pragma unroll
        for (int kk = 0; kk < 4; kk++) {
            #pragma unroll
            for (int p = 0; p < 4; p++) {
                uint32_t r0, r1, r2, r3;
                ldsm_x4_t(r0, r1, r2, r3, vb + (uint32_t)(kk*16*ALDK + p*16)*2u);
                mma16816(ov[2*p],   pa[kk], r0, r1);
                mma16816(ov[2*p+1], pa[kk], r2, r3);
            }
        }

        bar_sync(1 + g);
        if (i + 1 < ng) issue(g + 2*(i + 1));
    }

    // ---- merge the two groups ----
    __syncthreads();
    if (g == 1) {
        #pragma unroll
        for (int half = 0; half < 2; half++) {
            int rloc = wg*16 + (lane >> 2) + half*8;
            if ((lane & 3) == 0) { m1s[rloc] = mrun[half]; l1s[rloc] = lrun[half]; }
            #pragma unroll
            for (int nt = 0; nt < 8; nt++) {
                int c = nt*8 + (lane & 3)*2;
                ovs[rloc*65 + c]     = ov[nt][half*2];
                ovs[rloc*65 + c + 1] = ov[nt][half*2+1];
            }
        }
    }
    __syncthreads();
    if (g == 0) {
        #pragma unroll
        for (int half = 0; half < 2; half++) {
            int rloc = wg*16 + (lane >> 2) + half*8;
            float m1 = m1s[rloc], l1 = l1s[rloc];
            float ms = fmaxf(mrun[half], m1);
            float c0 = __expf(mrun[half] - ms);
            float c1 = __expf(m1 - ms);
            float inv = 1.0f / (lrun[half]*c0 + l1*c1);
            __nv_bfloat16* op = o + (size_t)(b*Tt + t0 + rloc)*Cc + h*64;
            #pragma unroll
            for (int nt = 0; nt < 8; nt++) {
                int c = nt*8 + (lane & 3)*2;
                float o0 = (ov[nt][half*2]  *c0 + ovs[rloc*65 + c]    *c1) * inv;
                float o1 = (ov[nt][half*2+1]*c0 + ovs[rloc*65 + c + 1]*c1) * inv;
                *(__nv_bfloat162*)(op + c) = __floats2bfloat162_rn(o0, o1);
            }
        }
    }
}

// ---------------- launch --------------------------------------------------------
extern "C" void kernel_launch(void* const* d_in, const int* in_sizes, int n_in,
                              void* d_out, int out_size)
{
    (void)in_sizes; (void)n_in; (void)out_size;
    const float* x      = (const float*)d_in[0];
    const float* ln1    = (const float*)d_in[2];
    const float* w_qkv  = (const float*)d_in[3];
    const float* b_qkv  = (const float*)d_in[4];
    const float* a_qkv  = (const float*)d_in[5];
    const float* w_ao   = (const float*)d_in[6];
    const float* b_ao   = (const float*)d_in[7];
    const float* a_ao   = (const float*)d_in[8];
    const float* ln2    = (const float*)d_in[9];
    const float* w_fc   = (const float*)d_in[10];
    const float* b_fc   = (const float*)d_in[11];
    const float* a_fc   = (const float*)d_in[12];
    const float* w_gate = (const float*)d_in[13];
    const float* b_gate = (const float*)d_in[14];
    const float* a_gate = (const float*)d_in[15];
    const float* w_proj = (const float*)d_in[16];
    const float* b_proj = (const float*)d_in[17];
    const float* a_proj = (const float*)d_in[18];
    float* out = (float*)d_out;

    float *x1, *rn, *part, *ropetab;
    __nv_bfloat16 *qkvb, *h, *o, *h2, *u, *wq, *wao, *wfcg, *wp;
    cudaGetSymbolAddress((void**)&x1,     g_x1);
    cudaGetSymbolAddress((void**)&rn,     g_rn);
    cudaGetSymbolAddress((void**)&part,   g_part);
    cudaGetSymbolAddress((void**)&ropetab,g_rope);
    cudaGetSymbolAddress((void**)&qkvb,   g_qkvb);
    cudaGetSymbolAddress((void**)&h,      g_h);
    cudaGetSymbolAddress((void**)&o,      g_o);
    cudaGetSymbolAddress((void**)&h2,     g_h2);
    cudaGetSymbolAddress((void**)&u,      g_u);
    cudaGetSymbolAddress((void**)&wq,     g_wq);
    cudaGetSymbolAddress((void**)&wao,    g_wao);
    cudaGetSymbolAddress((void**)&wfcg,   g_wfcg);
    cudaGetSymbolAddress((void**)&wp,     g_wp);

    const int GSMEM = GSTAGES * (128*GLDA + 64*GLDB) * (int)sizeof(__nv_bfloat16);
    cudaFuncSetAttribute(gemm_yat_mma<1, float, float>,
                         cudaFuncAttributeMaxDynamicSharedMemorySize, GSMEM);
    cudaFuncSetAttribute(gemm_yat_mma<3, __nv_bfloat16, float>,
                         cudaFuncAttributeMaxDynamicSharedMemorySize, GSMEM);
    cudaFuncSetAttribute(gemm_yat_mma<4, __nv_bfloat16, float>,
                         cudaFuncAttributeMaxDynamicSharedMemorySize, GSMEM);

    // 0. all weight conversions + colnorm partials + rope table (one launch)
    wconv_all<<<2560, 256>>>(w_qkv, w_ao, w_fc, w_gate, w_proj,
                             wq, wao, wfcg, wp, part, ropetab);

    // 1. LN1 -> h (bf16), rn
    ln_kernel<<<Mrows, 256>>>(x, ln1, h, rn);

    // 2. qkv = rope(yat(h @ w_qkv)) bf16, q pre-scaled by 1/8
    gemm_yat_mma<3, __nv_bfloat16, float><<<dim3(3*Cc/128, Mrows/128), 256, GSMEM>>>(
        h, wq, qkvb, rn, part + PART_QKV, Cc/64, b_qkv, a_qkv, nullptr, nullptr,
        ropetab, Mrows, 3*Cc, Cc);

    // 3. attention -> o (bf16)
    flash_attn_mma<<<dim3(Tt/64, Hh, Bb), 256>>>(qkvb, o);

    // 4. x1 = x + yat(o @ w_ao)
    gemm_yat_mma<1, float, float><<<dim3(Cc/128, Mrows/128), 256, GSMEM>>>(
        o, wao, x1, rn, part + PART_AO, Cc/64, b_ao, a_ao, nullptr, nullptr,
        x, Mrows, Cc, Cc);

    // 5. LN2 -> h2 (bf16), rn
    ln_kernel<<<Mrows, 256>>>(x1, ln2, h2, rn);

    // 6+7. u = gelu(yat(h2@w_gate)) * yat(h2@w_fc)  (one interleaved GEMM)
    gemm_yat_mma<4, __nv_bfloat16, float><<<dim3(NFCG/128, Mrows/128), 256, GSMEM>>>(
        h2, wfcg, u, rn, part + PART_FCG, Cc/64, b_fc, a_fc, b_gate, a_gate,
        (const float*)nullptr, Mrows, NFCG, Cc);

    // 8. out = x1 + yat(u @ w_proj)
    gemm_yat_mma<1, float, float><<<dim3(Cc/128, Mrows/128), 256, GSMEM>>>(
        u, wp, out, rn, part + PART_PROJ, HID/64, b_proj, a_proj, nullptr, nullptr,
        x1, Mrows, Cc, HID);
}

// round 16
// speedup vs baseline: 1.3098x; 1.1122x over previous
#include <cstdint>
#include <cstddef>
#include <cuda_runtime.h>
#include <cuda_bf16.h>
#include <cuda_fp8.h>
#include <math.h>

#define Bb   2
#define Tt   1024
#define Cc   768
#define Hh   12
#define HID  3072
#define NFCG 6144
#define Mrows (Bb*Tt)          // 2048

// part region offsets (floats)
#define PART_QKV  0            // 12*2304
#define PART_AO   27648        // 12*768
#define PART_FCG  36864        // 12*6144
#define PART_PROJ 110592       // 48*768
#define PART_TOT  147456

#define WSCALE 32.0f
#define WSCALE_INV 0.03125f

// ---------------- scratch (static device arrays; no cudaMalloc) ----------------
__device__ float g_x1  [Mrows*Cc];
__device__ float g_rn  [Mrows];
__device__ float g_part[PART_TOT];
__device__ float g_rope[Tt*64];
__device__ __nv_bfloat16 g_qkvb[Mrows*3*Cc];
__device__ __nv_fp8_e4m3 g_h  [Mrows*Cc];      // LN1 out (fp8)
__device__ __nv_bfloat16 g_o   [Mrows*Cc];
__device__ __nv_fp8_e4m3 g_h2 [Mrows*Cc];      // LN2 out (fp8)
__device__ __nv_bfloat16 g_u   [Mrows*HID];
__device__ __nv_fp8_e4m3 g_wq8 [3*Cc*Cc];      // transposed [N=2304][K=768], x32
__device__ __nv_fp8_e4m3 g_wfcg8[NFCG*Cc];     // transposed interleaved [6144][768], x32
__device__ __nv_bfloat16 g_wao [Cc*Cc];
__device__ __nv_bfloat16 g_wp  [HID*Cc];

// ---------------- helpers ------------------------------------------------------
__device__ __forceinline__ float blockReduceSum(float v) {
    __shared__ float sh[8];
    int lane = threadIdx.x & 31, w = threadIdx.x >> 5;
    #pragma unroll
    for (int o = 16; o; o >>= 1) v += __shfl_xor_sync(0xffffffffu, v, o);
    __syncthreads();
    if (lane == 0) sh[w] = v;
    __syncthreads();
    return sh[0]+sh[1]+sh[2]+sh[3]+sh[4]+sh[5]+sh[6]+sh[7];
}

__device__ __forceinline__ void blockReduceSum2(float& a, float& b) {
    __shared__ float sha[8], shb[8];
    int lane = threadIdx.x & 31, w = threadIdx.x >> 5;
    #pragma unroll
    for (int o = 16; o; o >>= 1) {
        a += __shfl_xor_sync(0xffffffffu, a, o);
        b += __shfl_xor_sync(0xffffffffu, b, o);
    }
    __syncthreads();
    if (lane == 0) { sha[w] = a; shb[w] = b; }
    __syncthreads();
    a = sha[0]+sha[1]+sha[2]+sha[3]+sha[4]+sha[5]+sha[6]+sha[7];
    b = shb[0]+shb[1]+shb[2]+shb[3]+shb[4]+shb[5]+shb[6]+shb[7];
}

__device__ __forceinline__ float gelu_tanh(float x) {
    float x3 = x * x * x;
    float t  = tanhf(0.7978845608028654f * (x + 0.044715f * x3));
    return 0.5f * x * (1.0f + t);
}

__device__ __forceinline__ float to_f32(float v)          { return v; }
__device__ __forceinline__ float to_f32(__nv_bfloat16 v)  { return __bfloat162float(v); }

__device__ __forceinline__ uint32_t pack2(float a, float b) {
    __nv_bfloat162 t = __floats2bfloat162_rn(a, b);
    return *(uint32_t*)&t;
}

// ---------------- PTX wrappers --------------------------------------------------
__device__ __forceinline__ void cp_async16(uint32_t smem, const void* gmem) {
    asm volatile("cp.async.cg.shared.global [%0],[%1],16;\n" :: "r"(smem), "l"(gmem));
}
__device__ __forceinline__ void cp_commit() {
    asm volatile("cp.async.commit_group;\n" ::: "memory");
}
__device__ __forceinline__ void cp_wait0() {
    asm volatile("cp.async.wait_group 0;\n" ::: "memory");
}
__device__ __forceinline__ void cp_wait1() {
    asm volatile("cp.async.wait_group 1;\n" ::: "memory");
}
__device__ __forceinline__ void bar_sync(int id) {
    asm volatile("bar.sync %0, 128;\n" :: "r"(id) : "memory");
}
__device__ __forceinline__ void ldsm_x4(uint32_t& r0, uint32_t& r1, uint32_t& r2, uint32_t& r3,
                                        uint32_t addr) {
    asm volatile("ldmatrix.sync.aligned.m8n8.x4.shared.b16 {%0,%1,%2,%3},[%4];\n"
                 : "=r"(r0), "=r"(r1), "=r"(r2), "=r"(r3) : "r"(addr));
}
__device__ __forceinline__ void ldsm_x4_t(uint32_t& r0, uint32_t& r1, uint32_t& r2, uint32_t& r3,
                                          uint32_t addr) {
    asm volatile("ldmatrix.sync.aligned.m8n8.x4.trans.shared.b16 {%0,%1,%2,%3},[%4];\n"
                 : "=r"(r0), "=r"(r1), "=r"(r2), "=r"(r3) : "r"(addr));
}
__device__ __forceinline__ void mma16816(float* d, const uint32_t* a, uint32_t b0, uint32_t b1) {
    asm volatile("mma.sync.aligned.m16n8k16.row.col.f32.bf16.bf16.f32 "
                 "{%0,%1,%2,%3},{%4,%5,%6,%7},{%8,%9},{%0,%1,%2,%3};\n"
                 : "+f"(d[0]), "+f"(d[1]), "+f"(d[2]), "+f"(d[3])
                 : "r"(a[0]), "r"(a[1]), "r"(a[2]), "r"(a[3]), "r"(b0), "r"(b1));
}
__device__ __forceinline__ void mma16832(float* d, const uint32_t* a, uint32_t b0, uint32_t b1) {
    asm volatile("mma.sync.aligned.m16n8k32.row.col.f32.e4m3.e4m3.f32 "
                 "{%0,%1,%2,%3},{%4,%5,%6,%7},{%8,%9},{%0,%1,%2,%3};\n"
                 : "+f"(d[0]), "+f"(d[1]), "+f"(d[2]), "+f"(d[3])
                 : "r"(a[0]), "r"(a[1]), "r"(a[2]), "r"(a[3]), "r"(b0), "r"(b1));
}

// ---------------- merged weight convert + colnorm partials + rope table ---------
__device__ __forceinline__ void wtile(const float* __restrict__ W,
                                      __nv_bfloat16* __restrict__ Wb,
                                      float* __restrict__ part, float* cred,
                                      int N, int k0, int n0)
{
    int tid = threadIdx.x;
    int n  = n0 + (tid & 63);
    int ks = tid >> 6;
    float s = 0.f;
    #pragma unroll 4
    for (int k = k0 + ks*16; k < k0 + ks*16 + 16; k++) {
        float v = W[(size_t)k * N + n];
        Wb[(size_t)k * N + n] = __float2bfloat16(v);
        s += v * v;
    }
    cred[tid] = s;
    __syncthreads();
    if (tid < 64)
        part[((size_t)(k0 >> 6)) * N + n0 + tid] =
            cred[tid] + cred[tid+64] + cred[tid+128] + cred[tid+192];
}

// transpose + fp8(x32) tile: source [K][Nsrc] (col sel via csel), out [Nout][K]
// INTER=0: src col = n0+n of W.  INTER=1: interleaved fc/gate (Nsrc=HID)
template<int INTER>
__device__ __forceinline__ void wtile_t8(const float* __restrict__ Wa,
                                         const float* __restrict__ Wb2,
                                         __nv_fp8_e4m3* __restrict__ Wt,
                                         float* __restrict__ part,
                                         float (*sm)[65], float* cred,
                                         int K, int Nout, int k0, int n0)
{
    int tid = threadIdx.x;
    #pragma unroll
    for (int i = 0; i < 16; i++) {
        int idx = tid + 256*i;
        int k = idx >> 6, n = idx & 63;
        int c = n0 + n;
        float v;
        if constexpr (INTER == 1) {
            const float* src = (c & 1) ? Wb2 : Wa;
            v = src[(size_t)(k0 + k) * HID + (c >> 1)];
        } else {
            v = Wa[(size_t)(k0 + k) * Nout + c];
        }
        sm[k][n] = v;
    }
    __syncthreads();
    {
        int n = tid & 63, kg = tid >> 6;
        float s = 0.f;
        #pragma unroll
        for (int j = 0; j < 16; j++) { float v = sm[kg*16 + j][n]; s += v*v; }
        cred[tid] = s;
    }
    __syncthreads();
    if (tid < 64)
        part[((size_t)(k0 >> 6)) * Nout + n0 + tid] =
            cred[tid] + cred[tid+64] + cred[tid+128] + cred[tid+192];
    #pragma unroll
    for (int i = 0; i < 16; i++) {
        int idx = tid + 256*i;
        int n = idx >> 6, k = idx & 63;
        Wt[(size_t)(n0 + n) * K + k0 + k] = __nv_fp8_e4m3(sm[k][n] * WSCALE);
    }
}

// tiles: qkv 432 | ao 144 | fcg 1152 | proj 576 | rope 256 => 2560 blocks
__global__ __launch_bounds__(256)
void wconv_all(const float* __restrict__ w_qkv, const float* __restrict__ w_ao,
               const float* __restrict__ w_fc,  const float* __restrict__ w_gate,
               const float* __restrict__ w_proj,
               __nv_fp8_e4m3* __restrict__ wq8, __nv_bfloat16* __restrict__ wao,
               __nv_fp8_e4m3* __restrict__ wfcg8, __nv_bfloat16* __restrict__ wp,
               float* __restrict__ part, float* __restrict__ rope)
{
    __shared__ float s_sm[64][65];
    __shared__ float s_cred[256];
    int bid = blockIdx.x;
    if (bid < 432) {            // qkv: K=768(12 kt), N=2304(36 nt) -> fp8 transposed
        int nt = bid % 36, kt = bid / 36;
        wtile_t8<0>(w_qkv, nullptr, wq8, part + PART_QKV, s_sm, s_cred,
                    Cc, 3*Cc, kt*64, nt*64);
    } else if (bid < 576) {     // ao: 12x12 bf16
        int l = bid - 432; int nt = l % 12, kt = l / 12;
        wtile(w_ao, wao, part + PART_AO, s_cred, Cc, kt*64, nt*64);
    } else if (bid < 1728) {    // fcg: K=768(12), N=6144(96) fp8 transposed interleaved
        int l = bid - 576; int nt = l % 96, kt = l / 96;
        wtile_t8<1>(w_fc, w_gate, wfcg8, part + PART_FCG, s_sm, s_cred,
                    Cc, NFCG, kt*64, nt*64);
    } else if (bid < 2304) {    // proj: K=3072(48), N=768(12) bf16
        int l = bid - 1728; int nt = l % 12, kt = l / 12;
        wtile(w_proj, wp, part + PART_PROJ, s_cred, Cc, kt*64, nt*64);
    } else {                    // rope table
        int i = (bid - 2304) * 256 + threadIdx.x;
        int t = i >> 6, d = i & 63, ii = d & 31;
        float fr  = expf(-(float)(2*ii) * (logf(10000.0f) / 64.0f));
        float ang = (float)t * fr;
        rope[i] = (d < 32) ? cosf(ang) : sinf(ang);
    }
}

// ---------------- LayerNorm -> fp8 h, fp32 rownorm ------------------------------
__global__ __launch_bounds__(256)
void ln_kernel(const float* __restrict__ x, const float* __restrict__ sc,
               __nv_fp8_e4m3* __restrict__ h, float* __restrict__ rn)
{
    int row = blockIdx.x;
    const float* xr = x + (size_t)row * Cc;
    int t = threadIdx.x;
    float v0 = xr[t], v1 = xr[t+256], v2 = xr[t+512];
    float s  = v0+v1+v2;
    float ss = v0*v0+v1*v1+v2*v2;
    blockReduceSum2(s, ss);
    float mu  = s  * (1.0f/768.0f);
    float var = ss * (1.0f/768.0f) - mu*mu;
    float rs  = rsqrtf(var + 1e-6f);
    float o0 = (v0-mu)*rs*sc[t];
    float o1 = (v1-mu)*rs*sc[t+256];
    float o2 = (v2-mu)*rs*sc[t+512];
    __nv_fp8_e4m3* hr = h + (size_t)row * Cc;
    hr[t]     = __nv_fp8_e4m3(o0);
    hr[t+256] = __nv_fp8_e4m3(o1);
    hr[t+512] = __nv_fp8_e4m3(o2);
    float hn = blockReduceSum(o0*o0+o1*o1+o2*o2);
    if (t == 0) rn[row] = hn;
}

// ---------------- fp8 tensor-core GEMM (8 warps, 64x32 warp tiles, BK=64) -------
// B transposed [N][K], weights pre-scaled x32 (y = acc/32)
// MODE 3: qkv rope (extra=rope table, q scaled 1/8); bf16 out
// MODE 4: interleaved fc/gate -> u = gelu(yat_gate)*yat_fc; bf16 out (N logical 3072)
#define F8LD   40          // b16 units per 64-fp8 row (80 B)
#define F8STGB (128u*80u)  // bytes per operand per stage
#define F8STAGES 3

template<int MODE>
__global__ __launch_bounds__(256, 2)
void gemm_yat_fp8(const __nv_fp8_e4m3* __restrict__ A, const __nv_fp8_e4m3* __restrict__ Bt,
                  __nv_bfloat16* __restrict__ out,
                  const float* __restrict__ rn, const float* __restrict__ part, int nch,
                  const float* __restrict__ bias, const float* __restrict__ alphap,
                  const float* __restrict__ bias2, const float* __restrict__ alphap2,
                  const float* __restrict__ extra,
                  int M, int N, int K)
{
    extern __shared__ char smem8[];
    __shared__ float cns[128];
    __shared__ float cred[256];

    const int tid = threadIdx.x;
    const int m0 = blockIdx.y * 128, n0 = blockIdx.x * 128;

    // cp.async: row = tid>>1 (A m-row / B n-row), 32B chunk (tid&1)
    const int lrow = tid >> 1, lc = (tid & 1) * 32;
    const char* Ag = (const char*)A  + (size_t)(m0 + lrow) * K + lc;
    const char* Bg = (const char*)Bt + (size_t)(n0 + lrow) * K + lc;
    const uint32_t S0 = (uint32_t)__cvta_generic_to_shared(smem8);
    const uint32_t Asw = S0 + (uint32_t)(lrow*80 + lc);
    const uint32_t Bs0 = S0 + F8STAGES * F8STGB;
    const uint32_t Bsw = Bs0 + (uint32_t)(lrow*80 + lc);

    const int lane = tid & 31, warp = tid >> 5;
    const int wm = (warp >> 2) * 64;
    const int wn = (warp & 3) * 32;

    const int KT = K >> 6;     // BK = 64 fp8

    auto issueT = [&](int kt, int stg) {
        const char* ag = Ag + (size_t)kt * 64;
        const char* bg = Bg + (size_t)kt * 64;
        uint32_t asd = Asw + (uint32_t)stg * F8STGB;
        uint32_t bsd = Bsw + (uint32_t)stg * F8STGB;
        cp_async16(asd, ag);        cp_async16(asd + 16u, ag + 16);
        cp_async16(bsd, bg);        cp_async16(bsd + 16u, bg + 16);
        cp_commit();
    };

    issueT(0, 0); issueT(1, 1);

    // column-norm slice reduce (overlaps cp.async)
    {
        int col  = tid & 127;
        int half = tid >> 7;
        float s = 0.f;
        for (int c = half; c < nch; c += 2)
            s += part[(size_t)c * N + n0 + col];
        cred[tid] = s;
    }
    __syncthreads();
    if (tid < 128) cns[tid] = cred[tid] + cred[tid + 128];

    float acc[4][4][4];
    #pragma unroll
    for (int i = 0; i < 4; i++)
        #pragma unroll
        for (int j = 0; j < 4; j++)
            #pragma unroll
            for (int e = 0; e < 4; e++) acc[i][j][e] = 0.f;

    // ldsm bases (byte addrs): row*80 + (lane>>4)*16
    const uint32_t a_mat = S0  + (uint32_t)((wm + (lane & 15)) * 80 + (lane >> 4) * 16);
    const uint32_t b_mat = Bs0 + (uint32_t)((wn + (lane & 15)) * 80 + (lane >> 4) * 16);

    int stg = 0, nstg = 2;
    for (int kt = 0; kt < KT; kt++) {
        if (kt + 1 < KT) cp_wait1(); else cp_wait0();
        __syncthreads();
        if (kt + 2 < KT) {
            issueT(kt + 2, nstg);
            nstg = (nstg == F8STAGES-1) ? 0 : nstg + 1;
        }

        uint32_t abase = a_mat + (uint32_t)stg * F8STGB;
        uint32_t bbase = b_mat + (uint32_t)stg * F8STGB;
        stg = (stg == F8STAGES-1) ? 0 : stg + 1;
        #pragma unroll
        for (int kk = 0; kk < 2; kk++) {       // two k32 steps per 64-fp8 tile
            uint32_t ra[4][4];
            uint32_t rb[2][4];
            #pragma unroll
            for (int mt = 0; mt < 4; mt++)
                ldsm_x4(ra[mt][0], ra[mt][1], ra[mt][2], ra[mt][3],
                        abase + (uint32_t)(mt*16*80 + kk*32));
            #pragma unroll
            for (int p = 0; p < 2; p++)
                ldsm_x4(rb[p][0], rb[p][1], rb[p][2], rb[p][3],
                        bbase + (uint32_t)(p*16*80 + kk*32));
            #pragma unroll
            for (int mt = 0; mt < 4; mt++)
                #pragma unroll
                for (int ng = 0; ng < 4; ng++)
                    mma16832(acc[mt][ng], ra[mt],
                             rb[ng>>1][ng&1], rb[ng>>1][(ng&1)+2]);
        }
    }
    __syncthreads();

    // --- yat epilogue (fp32); y = acc/32 ---
    float scN = (MODE == 4) ? 3072.f : (float)N;
    float sc  = powf(sqrtf(scN) / log1pf(scN), alphap[0]);
    float sc2 = 0.f;
    if constexpr (MODE == 4) sc2 = powf(sqrtf(3072.f) / log1pf(3072.f), alphap2[0]);

    #pragma unroll
    for (int mt = 0; mt < 4; mt++) {
        #pragma unroll
        for (int half = 0; half < 2; half++) {
            int mloc = wm + mt*16 + (lane >> 2) + half*8;
            int m = m0 + mloc;
            float rnv = rn[m];
            #pragma unroll
            for (int ng = 0; ng < 4; ng++) {
                int nloc = wn + ng*8 + (lane & 3)*2;
                int n = n0 + nloc;
                float y0 = acc[mt][ng][half*2 + 0] * WSCALE_INV;
                float y1 = acc[mt][ng][half*2 + 1] * WSCALE_INV;
                float d0 = rnv + cns[nloc]   - 2.0f*y0 + 1e-6f;
                float d1 = rnv + cns[nloc+1] - 2.0f*y1 + 1e-6f;
                if constexpr (MODE == 4) {
                    int j = n >> 1;
                    float vfc = (y0*y0/d0 + bias[j])  * sc;
                    float vgt = (y1*y1/d1 + bias2[j]) * sc2;
                    out[(size_t)m*HID + j] = __float2bfloat16(gelu_tanh(vgt) * vfc);
                } else {
                    float v0 = (y0*y0/d0 + bias[n])   * sc;
                    float v1 = (y1*y1/d1 + bias[n+1]) * sc;
                    if (n < 2*Cc) {
                        int t  = m % Tt;
                        int dd = n & 63;
                        float f0 = extra[t*64 + dd], f1 = extra[t*64 + dd + 1];
                        if (n < Cc) { f0 *= 0.125f; f1 *= 0.125f; }
                        v0 *= f0; v1 *= f1;
                    }
                    *(__nv_bfloat162*)(out + (size_t)m*N + n) =
                        __floats2bfloat162_rn(v0, v1);
                }
            }
        }
    }
}

// ---------------- bf16 tensor-core GEMM (R13 config) — MODE 1 only --------------
#define GLDA 40
#define GLDB 136
#define GSTAGES 3

__global__ __launch_bounds__(256, 2)
void gemm_yat_mma1(const __nv_bfloat16* __restrict__ A, const __nv_bfloat16* __restrict__ W,
                   float* __restrict__ out,
                   const float* __restrict__ part, int nch,
                   const float* __restrict__ bias, const float* __restrict__ alphap,
                   const float* __restrict__ extra,
                   int M, int N, int K)
{
    extern __shared__ __nv_bfloat16 smem[];
    __nv_bfloat16* As = smem;
    __nv_bfloat16* Bs = smem + GSTAGES*128*GLDA;
    __shared__ float cns[128];
    __shared__ float cred[256];
    __shared__ float rns[128];

    const int tid = threadIdx.x;
    const int m0 = blockIdx.y * 128, n0 = blockIdx.x * 128;

    const int a_row = tid >> 1, a_col = (tid & 1) * 16;
    const int b_row = tid >> 3, b_col = (tid & 7) * 16;
    const char* Ag = (const char*)(A + (size_t)(m0 + a_row) * K + a_col);
    const char* Bg = (const char*)(W + (size_t)b_row * N + n0 + b_col);
    const uint32_t As0 = (uint32_t)__cvta_generic_to_shared(As);
    const uint32_t Bs0 = (uint32_t)__cvta_generic_to_shared(Bs);
    const uint32_t Asw = As0 + (uint32_t)(a_row*GLDA + a_col)*2u;
    const uint32_t Bsw = Bs0 + (uint32_t)(b_row*GLDB + b_col)*2u;
    const uint32_t AS_STG = 128u*GLDA*2u, BS_STG = 32u*GLDB*2u;

    const int lane = tid & 31, warp = tid >> 5;
    const int wm = (warp >> 2) * 64;
    const int wn = (warp & 3) * 32;

    const int KT = K >> 5;

    auto issueT = [&](int kt, int stg) {
        const char* ag = Ag + (size_t)kt * 64;
        const char* bg = Bg + (size_t)kt * 32 * N * 2;
        uint32_t asd = Asw + (uint32_t)stg * AS_STG;
        uint32_t bsd = Bsw + (uint32_t)stg * BS_STG;
        cp_async16(asd, ag);        cp_async16(asd + 16u, ag + 16);
        cp_async16(bsd, bg);        cp_async16(bsd + 16u, bg + 16);
        cp_commit();
    };

    issueT(0, 0); issueT(1, 1);

    {
        int col  = tid & 127;
        int half = tid >> 7;
        float s = 0.f;
        for (int c = half; c < nch; c += 2)
            s += part[(size_t)c * N + n0 + col];
        cred[tid] = s;
    }
    __syncthreads();
    if (tid < 128) cns[tid] = cred[tid] + cred[tid + 128];

    float acc[4][4][4];
    #pragma unroll
    for (int i = 0; i < 4; i++)
        #pragma unroll
        for (int j = 0; j < 4; j++)
            #pragma unroll
            for (int e = 0; e < 4; e++) acc[i][j][e] = 0.f;

    const uint32_t a_mat = As0 + (uint32_t)(((wm + (lane & 15)) * GLDA) + (lane >> 4) * 8)*2u;
    const uint32_t b_mat = Bs0 + (uint32_t)(((lane & 15) * GLDB) + wn + (lane >> 4) * 8)*2u;

    float arn = 0.f;

    int stg = 0, nstg = 2;
    for (int kt = 0; kt < KT; kt++) {
        if (kt + 1 < KT) cp_wait1(); else cp_wait0();
        __syncthreads();
        if (kt + 2 < KT) {
            issueT(kt + 2, nstg);
            nstg = (nstg == GSTAGES-1) ? 0 : nstg + 1;
        }

        {
            const __nv_bfloat16* ap = As + (size_t)stg*128*GLDA + a_row*GLDA + a_col;
            #pragma unroll
            for (int i = 0; i < 8; i++) {
                __nv_bfloat162 v2 = *(const __nv_bfloat162*)(ap + 2*i);
                float f0 = __bfloat162float(v2.x), f1 = __bfloat162float(v2.y);
                arn = fmaf(f0, f0, fmaf(f1, f1, arn));
            }
        }

        uint32_t abase = a_mat + (uint32_t)stg * AS_STG;
        uint32_t bbase = b_mat + (uint32_t)stg * BS_STG;
        stg = (stg == GSTAGES-1) ? 0 : stg + 1;
        #pragma unroll
        for (int kk = 0; kk < 2; kk++) {
            uint32_t ra[4][4];
            uint32_t rb[2][4];
            #pragma unroll
            for (int mt = 0; mt < 4; mt++)
                ldsm_x4(ra[mt][0], ra[mt][1], ra[mt][2], ra[mt][3],
                        abase + (uint32_t)(mt*16*GLDA + kk*16)*2u);
            #pragma unroll
            for (int p = 0; p < 2; p++)
                ldsm_x4_t(rb[p][0], rb[p][1], rb[p][2], rb[p][3],
                          bbase + (uint32_t)(kk*16*GLDB + p*16)*2u);
            #pragma unroll
            for (int mt = 0; mt < 4; mt++)
                #pragma unroll
                for (int nt = 0; nt < 4; nt++)
                    mma16816(acc[mt][nt], ra[mt],
                             rb[nt>>1][(nt&1)*2], rb[nt>>1][(nt&1)*2 + 1]);
        }
    }

    arn += __shfl_xor_sync(0xffffffffu, arn, 1);
    if ((tid & 1) == 0) rns[a_row] = arn;
    __syncthreads();

    float sc = powf(sqrtf((float)N) / log1pf((float)N), alphap[0]);
    #pragma unroll
    for (int mt = 0; mt < 4; mt++) {
        #pragma unroll
        for (int half = 0; half < 2; half++) {
            int mloc = wm + mt*16 + (lane >> 2) + half*8;
            int m = m0 + mloc;
            float rnv = rns[mloc];
            #pragma unroll
            for (int nt = 0; nt < 4; nt++) {
                int nloc = wn + nt*8 + (lane & 3)*2;
                int n = n0 + nloc;
                float y0 = acc[mt][nt][half*2 + 0];
                float y1 = acc[mt][nt][half*2 + 1];
                float d0 = rnv + cns[nloc]   - 2.0f*y0 + 1e-6f;
                float d1 = rnv + cns[nloc+1] - 2.0f*y1 + 1e-6f;
                float v0 = (y0*y0/d0 + bias[n])   * sc + extra[(size_t)m*N + n];
                float v1 = (y1*y1/d1 + bias[n+1]) * sc + extra[(size_t)m*N + n + 1];
                *(float2*)(out + (size_t)m*N + n) = make_float2(v0, v1);
            }
        }
    }
}

// ---------------- bf16 mma flash attention: 2-group split-KV, 256 threads -------
#define ALDK 72
__global__ __launch_bounds__(256)
void flash_attn_mma(const __nv_bfloat16* __restrict__ qkv, __nv_bfloat16* __restrict__ o)
{
    __shared__ __nv_bfloat16 KVs[4][64*ALDK];
    __shared__ float m1s[64], l1s[64];
    float* ovs = (float*)&KVs[2][0];

    const int tid  = threadIdx.x;
    const int g    = tid >> 7;
    const int gtid = tid & 127;
    const int lane = tid & 31, warp = tid >> 5;
    const int wg   = warp & 3;
    const int qt = (int)gridDim.x - 1 - (int)blockIdx.x;
    const int h = blockIdx.y, b = blockIdx.z;
    const int t0 = qt * 64;
    const int RS = 3*Cc;
    const int ng = (qt + 2 - g) >> 1;

    const int krow = gtid >> 1, koff = (gtid & 1) * 32;
    const __nv_bfloat16* kgbase = qkv + (size_t)(b*Tt + krow) * RS + Cc + h*64 + koff;
    const uint32_t kbL = (uint32_t)__cvta_generic_to_shared(&KVs[2*g][0]);
    const uint32_t vbL = (uint32_t)__cvta_generic_to_shared(&KVs[2*g+1][0]);
    const uint32_t ksw = kbL + (uint32_t)(krow*ALDK + koff)*2u;
    const uint32_t vsw = vbL + (uint32_t)(krow*ALDK + koff)*2u;

    auto issue = [&](int jt) {
        const __nv_bfloat16* kp = kgbase + (size_t)jt * 64 * RS;
        const __nv_bfloat16* vp = kp + Cc;
        #pragma unroll
        for (int i = 0; i < 4; i++) {
            cp_async16(ksw + i*16u, kp + i*8);
            cp_async16(vsw + i*16u, vp + i*8);
        }
        cp_commit();
    };

    if (ng > 0) issue(g);

    uint32_t qa[4][4];
    {
        int r = t0 + wg*16 + (lane >> 2);
        const __nv_bfloat16* q0 = qkv + (size_t)(b*Tt + r) * RS + h*64;
        const __nv_bfloat16* q8 = q0 + (size_t)8 * RS;
        #pragma unroll
        for (int kk = 0; kk < 4; kk++) {
            int c = kk*16 + (lane & 3)*2;
            qa[kk][0] = *(const uint32_t*)(q0 + c);
            qa[kk][1] = *(const uint32_t*)(q8 + c);
            qa[kk][2] = *(const uint32_t*)(q0 + c + 8);
            qa[kk][3] = *(const uint32_t*)(q8 + c + 8);
        }
    }

    float s[8][4], ov[8][4];
    float mrun[2] = {-1e30f, -1e30f}, lrun[2] = {0.f, 0.f};
    #pragma unroll
    for (int nt = 0; nt < 8; nt++)
        #pragma unroll
        for (int e = 0; e < 4; e++) ov[nt][e] = 0.f;

    const uint32_t kofs = (uint32_t)(((lane & 7) + ((lane >> 4) << 3)) * ALDK + (((lane >> 3) & 1) << 3)) * 2u;
    const uint32_t vofs = (uint32_t)((lane & 15) * ALDK + ((lane >> 4) << 3)) * 2u;

    for (int i = 0; i < ng; i++) {
        int jt = g + 2*i;
        cp_wait0();
        bar_sync(1 + g);

        #pragma unroll
        for (int nt = 0; nt < 8; nt++)
            #pragma unroll
            for (int e = 0; e < 4; e++) s[nt][e] = 0.f;
        uint32_t kb = kbL + kofs;
        #pragma unroll
        for (int kk = 0; kk < 4; kk++) {
            #pragma unroll
            for (int p = 0; p < 4; p++) {
                uint32_t r0, r1, r2, r3;
                ldsm_x4(r0, r1, r2, r3, kb + (uint32_t)(p*16*ALDK + kk*16)*2u);
                mma16816(s[2*p],   qa[kk], r0, r1);
                mma16816(s[2*p+1], qa[kk], r2, r3);
            }
        }

        bool diag = (jt == qt);
        #pragma unroll
        for (int half = 0; half < 2; half++) {
            int grow = t0 + wg*16 + (lane >> 2) + half*8;
            float mx = mrun[half];
            #pragma unroll
            for (int nt = 0; nt < 8; nt++) {
                float v0 = s[nt][half*2], v1 = s[nt][half*2+1];
                if (diag) {
                    int c0 = jt*64 + nt*8 + (lane & 3)*2;
                    if (c0     > grow) v0 = -1e30f;
                    if (c0 + 1 > grow) v1 = -1e30f;
                    s[nt][half*2] = v0; s[nt][half*2+1] = v1;
                }
                mx = fmaxf(mx, fmaxf(v0, v1));
            }
            mx = fmaxf(mx, __shfl_xor_sync(0xffffffffu, mx, 1));
            mx = fmaxf(mx, __shfl_xor_sync(0xffffffffu, mx, 2));
            float corr = __expf(mrun[half] - mx);
            mrun[half] = mx;
            float ls = 0.f;
            #pragma unroll
            for (int nt = 0; nt < 8; nt++) {
                float p0 = __expf(s[nt][half*2]   - mx);
                float p1 = __expf(s[nt][half*2+1] - mx);
                s[nt][half*2] = p0; s[nt][half*2+1] = p1;
                ls += p0 + p1;
            }
            ls += __shfl_xor_sync(0xffffffffu, ls, 1);
            ls += __shfl_xor_sync(0xffffffffu, ls, 2);
            lrun[half] = lrun[half]*corr + ls;
            #pragma unroll
            for (int nt = 0; nt < 8; nt++) { ov[nt][half*2] *= corr; ov[nt][half*2+1] *= corr; }
        }

        uint32_t pa[4][4];
        #pragma unroll
        for (int kk = 0; kk < 4; kk++) {
            pa[kk][0] = pack2(s[2*kk][0],   s[2*kk][1]);
            pa[kk][1] = pack2(s[2*kk][2],   s[2*kk][3]);
            pa[kk][2] = pack2(s[2*kk+1][0], s[2*kk+1][1]);
            pa[kk][3] = pack2(s[2*kk+1][2], s[2*kk+1][3]);
        }
        uint32_t vb = vbL + vofs;
        #pragma unroll
        for (int kk = 0; kk < 4; kk++) {
            #pragma unroll
            for (int p = 0; p < 4; p++) {
                uint32_t r0, r1, r2, r3;
                ldsm_x4_t(r0, r1, r2, r3, vb + (uint32_t)(kk*16*ALDK + p*16)*2u);
                mma16816(ov[2*p],   pa[kk], r0, r1);
                mma16816(ov[2*p+1], pa[kk], r2, r3);
            }
        }

        bar_sync(1 + g);
        if (i + 1 < ng) issue(g + 2*(i + 1));
    }

    __syncthreads();
    if (g == 1) {
        #pragma unroll
        for (int half = 0; half < 2; half++) {
            int rloc = wg*16 + (lane >> 2) + half*8;
            if ((lane & 3) == 0) { m1s[rloc] = mrun[half]; l1s[rloc] = lrun[half]; }
            #pragma unroll
            for (int nt = 0; nt < 8; nt++) {
                int c = nt*8 + (lane & 3)*2;
                ovs[rloc*65 + c]     = ov[nt][half*2];
                ovs[rloc*65 + c + 1] = ov[nt][half*2+1];
            }
        }
    }
    __syncthreads();
    if (g == 0) {
        #pragma unroll
        for (int half = 0; half < 2; half++) {
            int rloc = wg*16 + (lane >> 2) + half*8;
            float m1 = m1s[rloc], l1 = l1s[rloc];
            float ms = fmaxf(mrun[half], m1);
            float c0 = __expf(mrun[half] - ms);
            float c1 = __expf(m1 - ms);
            float inv = 1.0f / (lrun[half]*c0 + l1*c1);
            __nv_bfloat16* op = o + (size_t)(b*Tt + t0 + rloc)*Cc + h*64;
            #pragma unroll
            for (int nt = 0; nt < 8; nt++) {
                int c = nt*8 + (lane & 3)*2;
                float o0 = (ov[nt][half*2]  *c0 + ovs[rloc*65 + c]    *c1) * inv;
                float o1 = (ov[nt][half*2+1]*c0 + ovs[rloc*65 + c + 1]*c1) * inv;
                *(__nv_bfloat162*)(op + c) = __floats2bfloat162_rn(o0, o1);
            }
        }
    }
}

// ---------------- launch --------------------------------------------------------
extern "C" void kernel_launch(void* const* d_in, const int* in_sizes, int n_in,
                              void* d_out, int out_size)
{
    (void)in_sizes; (void)n_in; (void)out_size;
    const float* x      = (const float*)d_in[0];
    const float* ln1    = (const float*)d_in[2];
    const float* w_qkv  = (const float*)d_in[3];
    const float* b_qkv  = (const float*)d_in[4];
    const float* a_qkv  = (const float*)d_in[5];
    const float* w_ao   = (const float*)d_in[6];
    const float* b_ao   = (const float*)d_in[7];
    const float* a_ao   = (const float*)d_in[8];
    const float* ln2    = (const float*)d_in[9];
    const float* w_fc   = (const float*)d_in[10];
    const float* b_fc   = (const float*)d_in[11];
    const float* a_fc   = (const float*)d_in[12];
    const float* w_gate = (const float*)d_in[13];
    const float* b_gate = (const float*)d_in[14];
    const float* a_gate = (const float*)d_in[15];
    const float* w_proj = (const float*)d_in[16];
    const float* b_proj = (const float*)d_in[17];
    const float* a_proj = (const float*)d_in[18];
    float* out = (float*)d_out;

    float *x1, *rn, *part, *ropetab;
    __nv_bfloat16 *qkvb, *o, *u, *wao, *wp;
    __nv_fp8_e4m3 *h, *h2, *wq8, *wfcg8;
    cudaGetSymbolAddress((void**)&x1,     g_x1);
    cudaGetSymbolAddress((void**)&rn,     g_rn);
    cudaGetSymbolAddress((void**)&part,   g_part);
    cudaGetSymbolAddress((void**)&ropetab,g_rope);
    cudaGetSymbolAddress((void**)&qkvb,   g_qkvb);
    cudaGetSymbolAddress((void**)&h,      g_h);
    cudaGetSymbolAddress((void**)&o,      g_o);
    cudaGetSymbolAddress((void**)&h2,     g_h2);
    cudaGetSymbolAddress((void**)&u,      g_u);
    cudaGetSymbolAddress((void**)&wq8,    g_wq8);
    cudaGetSymbolAddress((void**)&wao,    g_wao);
    cudaGetSymbolAddress((void**)&wfcg8,  g_wfcg8);
    cudaGetSymbolAddress((void**)&wp,     g_wp);

    const int GSMEM  = GSTAGES * (128*GLDA + 32*GLDB) * (int)sizeof(__nv_bfloat16);
    const int F8SMEM = F8STAGES * 2 * (int)F8STGB;
    cudaFuncSetAttribute(gemm_yat_mma1,
                         cudaFuncAttributeMaxDynamicSharedMemorySize, GSMEM);
    cudaFuncSetAttribute(gemm_yat_fp8<3>,
                         cudaFuncAttributeMaxDynamicSharedMemorySize, F8SMEM);
    cudaFuncSetAttribute(gemm_yat_fp8<4>,
                         cudaFuncAttributeMaxDynamicSharedMemorySize, F8SMEM);

    // 0. all weight conversions + colnorm partials + rope table (one launch)
    wconv_all<<<2560, 256>>>(w_qkv, w_ao, w_fc, w_gate, w_proj,
                             wq8, wao, wfcg8, wp, part, ropetab);

    // 1. LN1 -> h (fp8), rn
    ln_kernel<<<Mrows, 256>>>(x, ln1, h, rn);

    // 2. qkv = rope(yat(h @ w_qkv)) bf16, q pre-scaled by 1/8   [fp8 GEMM]
    gemm_yat_fp8<3><<<dim3(3*Cc/128, Mrows/128), 256, F8SMEM>>>(
        h, wq8, qkvb, rn, part + PART_QKV, Cc/64, b_qkv, a_qkv, nullptr, nullptr,
        ropetab, Mrows, 3*Cc, Cc);

    // 3. attention -> o (bf16)
    flash_attn_mma<<<dim3(Tt/64, Hh, Bb), 256>>>(qkvb, o);

    // 4. x1 = x + yat(o @ w_ao)   [bf16 GEMM, in-kernel rownorm]
    gemm_yat_mma1<<<dim3(Cc/128, Mrows/128), 256, GSMEM>>>(
        o, wao, x1, part + PART_AO, Cc/64, b_ao, a_ao, x, Mrows, Cc, Cc);

    // 5. LN2 -> h2 (fp8), rn
    ln_kernel<<<Mrows, 256>>>(x1, ln2, h2, rn);

    // 6+7. u = gelu(yat(h2@w_gate)) * yat(h2@w_fc)   [fp8 interleaved GEMM]
    gemm_yat_fp8<4><<<dim3(NFCG/128, Mrows/128), 256, F8SMEM>>>(
        h2, wfcg8, u, rn, part + PART_FCG, Cc/64, b_fc, a_fc, b_gate, a_gate,
        (const float*)nullptr, Mrows, NFCG, Cc);

    // 8. out = x1 + yat(u @ w_proj)   [bf16 GEMM, in-kernel rownorm]
    gemm_yat_mma1<<<dim3(Cc/128, Mrows/128), 256, GSMEM>>>(
        u, wp, out, part + PART_PROJ, HID/64, b_proj, a_proj, x1, Mrows, Cc, HID);
}

// round 17
// speedup vs baseline: 1.3515x; 1.0318x over previous
#include <cstdint>
#include <cstddef>
#include <cuda_runtime.h>
#include <cuda_bf16.h>
#include <cuda_fp8.h>
#include <math.h>

#define Bb   2
#define Tt   1024
#define Cc   768
#define Hh   12
#define HID  3072
#define NFCG 6144
#define Mrows (Bb*Tt)          // 2048

// part region offsets (floats)
#define PART_QKV  0            // 12*2304
#define PART_AO   27648        // 12*768
#define PART_FCG  36864        // 12*6144
#define PART_PROJ 110592       // 48*768
#define PART_TOT  147456

#define WSCALE 32.0f
#define WSCALE_INV 0.03125f

// ---------------- scratch (static device arrays; no cudaMalloc) ----------------
__device__ float g_x1  [Mrows*Cc];
__device__ float g_rn  [Mrows];
__device__ float g_part[PART_TOT];
__device__ float g_rope[Tt*64];
__device__ __nv_bfloat16 g_qkvb[Mrows*3*Cc];
__device__ __nv_fp8_e4m3 g_h  [Mrows*Cc];
__device__ __nv_bfloat16 g_o   [Mrows*Cc];
__device__ __nv_fp8_e4m3 g_h2 [Mrows*Cc];
__device__ __nv_bfloat16 g_u   [Mrows*HID];
__device__ __nv_fp8_e4m3 g_wq8 [3*Cc*Cc];      // transposed [2304][768], x32
__device__ __nv_fp8_e4m3 g_wfcg8[NFCG*Cc];     // transposed interleaved [6144][768], x32
__device__ __nv_bfloat16 g_wao [Cc*Cc];
__device__ __nv_bfloat16 g_wp  [HID*Cc];

// ---------------- helpers ------------------------------------------------------
__device__ __forceinline__ float blockReduceSum(float v) {
    __shared__ float sh[8];
    int lane = threadIdx.x & 31, w = threadIdx.x >> 5;
    #pragma unroll
    for (int o = 16; o; o >>= 1) v += __shfl_xor_sync(0xffffffffu, v, o);
    __syncthreads();
    if (lane == 0) sh[w] = v;
    __syncthreads();
    return sh[0]+sh[1]+sh[2]+sh[3]+sh[4]+sh[5]+sh[6]+sh[7];
}

__device__ __forceinline__ void blockReduceSum2(float& a, float& b) {
    __shared__ float sha[8], shb[8];
    int lane = threadIdx.x & 31, w = threadIdx.x >> 5;
    #pragma unroll
    for (int o = 16; o; o >>= 1) {
        a += __shfl_xor_sync(0xffffffffu, a, o);
        b += __shfl_xor_sync(0xffffffffu, b, o);
    }
    __syncthreads();
    if (lane == 0) { sha[w] = a; shb[w] = b; }
    __syncthreads();
    a = sha[0]+sha[1]+sha[2]+sha[3]+sha[4]+sha[5]+sha[6]+sha[7];
    b = shb[0]+shb[1]+shb[2]+shb[3]+shb[4]+shb[5]+shb[6]+shb[7];
}

__device__ __forceinline__ float gelu_tanh(float x) {
    float x3 = x * x * x;
    float t  = tanhf(0.7978845608028654f * (x + 0.044715f * x3));
    return 0.5f * x * (1.0f + t);
}

__device__ __forceinline__ uint32_t pack2(float a, float b) {
    __nv_bfloat162 t = __floats2bfloat162_rn(a, b);
    return *(uint32_t*)&t;
}

// ---------------- PTX wrappers --------------------------------------------------
__device__ __forceinline__ void cp_async16(uint32_t smem, const void* gmem) {
    asm volatile("cp.async.cg.shared.global [%0],[%1],16;\n" :: "r"(smem), "l"(gmem));
}
__device__ __forceinline__ void cp_commit() {
    asm volatile("cp.async.commit_group;\n" ::: "memory");
}
__device__ __forceinline__ void cp_wait0() {
    asm volatile("cp.async.wait_group 0;\n" ::: "memory");
}
__device__ __forceinline__ void cp_wait1() {
    asm volatile("cp.async.wait_group 1;\n" ::: "memory");
}
__device__ __forceinline__ void bar_sync(int id) {
    asm volatile("bar.sync %0, 128;\n" :: "r"(id) : "memory");
}
__device__ __forceinline__ void ldsm_x4(uint32_t& r0, uint32_t& r1, uint32_t& r2, uint32_t& r3,
                                        uint32_t addr) {
    asm volatile("ldmatrix.sync.aligned.m8n8.x4.shared.b16 {%0,%1,%2,%3},[%4];\n"
                 : "=r"(r0), "=r"(r1), "=r"(r2), "=r"(r3) : "r"(addr));
}
__device__ __forceinline__ void ldsm_x4_t(uint32_t& r0, uint32_t& r1, uint32_t& r2, uint32_t& r3,
                                          uint32_t addr) {
    asm volatile("ldmatrix.sync.aligned.m8n8.x4.trans.shared.b16 {%0,%1,%2,%3},[%4];\n"
                 : "=r"(r0), "=r"(r1), "=r"(r2), "=r"(r3) : "r"(addr));
}
__device__ __forceinline__ void mma16816(float* d, const uint32_t* a, uint32_t b0, uint32_t b1) {
    asm volatile("mma.sync.aligned.m16n8k16.row.col.f32.bf16.bf16.f32 "
                 "{%0,%1,%2,%3},{%4,%5,%6,%7},{%8,%9},{%0,%1,%2,%3};\n"
                 : "+f"(d[0]), "+f"(d[1]), "+f"(d[2]), "+f"(d[3])
                 : "r"(a[0]), "r"(a[1]), "r"(a[2]), "r"(a[3]), "r"(b0), "r"(b1));
}
__device__ __forceinline__ void mma16832(float* d, const uint32_t* a, uint32_t b0, uint32_t b1) {
    asm volatile("mma.sync.aligned.m16n8k32.row.col.f32.e4m3.e4m3.f32 "
                 "{%0,%1,%2,%3},{%4,%5,%6,%7},{%8,%9},{%0,%1,%2,%3};\n"
                 : "+f"(d[0]), "+f"(d[1]), "+f"(d[2]), "+f"(d[3])
                 : "r"(a[0]), "r"(a[1]), "r"(a[2]), "r"(a[3]), "r"(b0), "r"(b1));
}

// ---------------- merged weight convert + colnorm partials + rope table ---------
__device__ __forceinline__ void wtile(const float* __restrict__ W,
                                      __nv_bfloat16* __restrict__ Wb,
                                      float* __restrict__ part, float* cred,
                                      int N, int k0, int n0)
{
    int tid = threadIdx.x;
    int n  = n0 + (tid & 63);
    int ks = tid >> 6;
    float s = 0.f;
    #pragma unroll 4
    for (int k = k0 + ks*16; k < k0 + ks*16 + 16; k++) {
        float v = W[(size_t)k * N + n];
        Wb[(size_t)k * N + n] = __float2bfloat16(v);
        s += v * v;
    }
    cred[tid] = s;
    __syncthreads();
    if (tid < 64)
        part[((size_t)(k0 >> 6)) * N + n0 + tid] =
            cred[tid] + cred[tid+64] + cred[tid+128] + cred[tid+192];
}

template<int INTER>
__device__ __forceinline__ void wtile_t8(const float* __restrict__ Wa,
                                         const float* __restrict__ Wb2,
                                         __nv_fp8_e4m3* __restrict__ Wt,
                                         float* __restrict__ part,
                                         float (*sm)[65], float* cred,
                                         int K, int Nout, int k0, int n0)
{
    int tid = threadIdx.x;
    #pragma unroll
    for (int i = 0; i < 16; i++) {
        int idx = tid + 256*i;
        int k = idx >> 6, n = idx & 63;
        int c = n0 + n;
        float v;
        if constexpr (INTER == 1) {
            const float* src = (c & 1) ? Wb2 : Wa;
            v = src[(size_t)(k0 + k) * HID + (c >> 1)];
        } else {
            v = Wa[(size_t)(k0 + k) * Nout + c];
        }
        sm[k][n] = v;
    }
    __syncthreads();
    {
        int n = tid & 63, kg = tid >> 6;
        float s = 0.f;
        #pragma unroll
        for (int j = 0; j < 16; j++) { float v = sm[kg*16 + j][n]; s += v*v; }
        cred[tid] = s;
    }
    __syncthreads();
    if (tid < 64)
        part[((size_t)(k0 >> 6)) * Nout + n0 + tid] =
            cred[tid] + cred[tid+64] + cred[tid+128] + cred[tid+192];
    #pragma unroll
    for (int i = 0; i < 16; i++) {
        int idx = tid + 256*i;
        int n = idx >> 6, k = idx & 63;
        Wt[(size_t)(n0 + n) * K + k0 + k] = __nv_fp8_e4m3(sm[k][n] * WSCALE);
    }
}

// tiles: qkv 432 | ao 144 | fcg 1152 | proj 576 | rope 256 => 2560 blocks
__global__ __launch_bounds__(256)
void wconv_all(const float* __restrict__ w_qkv, const float* __restrict__ w_ao,
               const float* __restrict__ w_fc,  const float* __restrict__ w_gate,
               const float* __restrict__ w_proj,
               __nv_fp8_e4m3* __restrict__ wq8, __nv_bfloat16* __restrict__ wao,
               __nv_fp8_e4m3* __restrict__ wfcg8, __nv_bfloat16* __restrict__ wp,
               float* __restrict__ part, float* __restrict__ rope)
{
    __shared__ float s_sm[64][65];
    __shared__ float s_cred[256];
    int bid = blockIdx.x;
    if (bid < 432) {
        int nt = bid % 36, kt = bid / 36;
        wtile_t8<0>(w_qkv, nullptr, wq8, part + PART_QKV, s_sm, s_cred,
                    Cc, 3*Cc, kt*64, nt*64);
    } else if (bid < 576) {
        int l = bid - 432; int nt = l % 12, kt = l / 12;
        wtile(w_ao, wao, part + PART_AO, s_cred, Cc, kt*64, nt*64);
    } else if (bid < 1728) {
        int l = bid - 576; int nt = l % 96, kt = l / 96;
        wtile_t8<1>(w_fc, w_gate, wfcg8, part + PART_FCG, s_sm, s_cred,
                    Cc, NFCG, kt*64, nt*64);
    } else if (bid < 2304) {
        int l = bid - 1728; int nt = l % 12, kt = l / 12;
        wtile(w_proj, wp, part + PART_PROJ, s_cred, Cc, kt*64, nt*64);
    } else {
        int i = (bid - 2304) * 256 + threadIdx.x;
        int t = i >> 6, d = i & 63, ii = d & 31;
        float fr  = expf(-(float)(2*ii) * (logf(10000.0f) / 64.0f));
        float ang = (float)t * fr;
        rope[i] = (d < 32) ? cosf(ang) : sinf(ang);
    }
}

// ---------------- LayerNorm -> fp8 h, fp32 rownorm ------------------------------
__global__ __launch_bounds__(256)
void ln_kernel(const float* __restrict__ x, const float* __restrict__ sc,
               __nv_fp8_e4m3* __restrict__ h, float* __restrict__ rn)
{
    int row = blockIdx.x;
    const float* xr = x + (size_t)row * Cc;
    int t = threadIdx.x;
    float v0 = xr[t], v1 = xr[t+256], v2 = xr[t+512];
    float s  = v0+v1+v2;
    float ss = v0*v0+v1*v1+v2*v2;
    blockReduceSum2(s, ss);
    float mu  = s  * (1.0f/768.0f);
    float var = ss * (1.0f/768.0f) - mu*mu;
    float rs  = rsqrtf(var + 1e-6f);
    float o0 = (v0-mu)*rs*sc[t];
    float o1 = (v1-mu)*rs*sc[t+256];
    float o2 = (v2-mu)*rs*sc[t+512];
    __nv_fp8_e4m3* hr = h + (size_t)row * Cc;
    hr[t]     = __nv_fp8_e4m3(o0);
    hr[t+256] = __nv_fp8_e4m3(o1);
    hr[t+512] = __nv_fp8_e4m3(o2);
    float hn = blockReduceSum(o0*o0+o1*o1+o2*o2);
    if (t == 0) rn[row] = hn;
}

// ---------------- fp8 tensor-core GEMM (8 warps, 64x32 warp tiles, BK=64) -------
#define F8STGB (128u*80u)
#define F8STAGES 3

template<int MODE>
__global__ __launch_bounds__(256, 2)
void gemm_yat_fp8(const __nv_fp8_e4m3* __restrict__ A, const __nv_fp8_e4m3* __restrict__ Bt,
                  __nv_bfloat16* __restrict__ out,
                  const float* __restrict__ rn, const float* __restrict__ part, int nch,
                  const float* __restrict__ bias, const float* __restrict__ alphap,
                  const float* __restrict__ bias2, const float* __restrict__ alphap2,
                  const float* __restrict__ extra,
                  int M, int N, int K)
{
    extern __shared__ char smem8[];
    __shared__ float cns[128];
    __shared__ float cred[256];

    const int tid = threadIdx.x;
    const int m0 = blockIdx.y * 128, n0 = blockIdx.x * 128;

    const int lrow = tid >> 1, lc = (tid & 1) * 32;
    const char* Ag = (const char*)A  + (size_t)(m0 + lrow) * K + lc;
    const char* Bg = (const char*)Bt + (size_t)(n0 + lrow) * K + lc;
    const uint32_t S0 = (uint32_t)__cvta_generic_to_shared(smem8);
    const uint32_t Asw = S0 + (uint32_t)(lrow*80 + lc);
    const uint32_t Bs0 = S0 + F8STAGES * F8STGB;
    const uint32_t Bsw = Bs0 + (uint32_t)(lrow*80 + lc);

    const int lane = tid & 31, warp = tid >> 5;
    const int wm = (warp >> 2) * 64;
    const int wn = (warp & 3) * 32;

    const int KT = K >> 6;

    auto issueT = [&](int kt, int stg) {
        const char* ag = Ag + (size_t)kt * 64;
        const char* bg = Bg + (size_t)kt * 64;
        uint32_t asd = Asw + (uint32_t)stg * F8STGB;
        uint32_t bsd = Bsw + (uint32_t)stg * F8STGB;
        cp_async16(asd, ag);        cp_async16(asd + 16u, ag + 16);
        cp_async16(bsd, bg);        cp_async16(bsd + 16u, bg + 16);
        cp_commit();
    };

    issueT(0, 0); issueT(1, 1);

    {
        int col  = tid & 127;
        int half = tid >> 7;
        float s = 0.f;
        for (int c = half; c < nch; c += 2)
            s += part[(size_t)c * N + n0 + col];
        cred[tid] = s;
    }
    __syncthreads();
    if (tid < 128) cns[tid] = cred[tid] + cred[tid + 128];

    float acc[4][4][4];
    #pragma unroll
    for (int i = 0; i < 4; i++)
        #pragma unroll
        for (int j = 0; j < 4; j++)
            #pragma unroll
            for (int e = 0; e < 4; e++) acc[i][j][e] = 0.f;

    const uint32_t a_mat = S0  + (uint32_t)((wm + (lane & 15)) * 80 + (lane >> 4) * 16);
    const uint32_t b_mat = Bs0 + (uint32_t)((wn + (lane & 15)) * 80 + (lane >> 4) * 16);

    int stg = 0, nstg = 2;
    for (int kt = 0; kt < KT; kt++) {
        if (kt + 1 < KT) cp_wait1(); else cp_wait0();
        __syncthreads();
        if (kt + 2 < KT) {
            issueT(kt + 2, nstg);
            nstg = (nstg == F8STAGES-1) ? 0 : nstg + 1;
        }

        uint32_t abase = a_mat + (uint32_t)stg * F8STGB;
        uint32_t bbase = b_mat + (uint32_t)stg * F8STGB;
        stg = (stg == F8STAGES-1) ? 0 : stg + 1;
        #pragma unroll
        for (int kk = 0; kk < 2; kk++) {
            uint32_t ra[4][4];
            uint32_t rb[2][4];
            #pragma unroll
            for (int mt = 0; mt < 4; mt++)
                ldsm_x4(ra[mt][0], ra[mt][1], ra[mt][2], ra[mt][3],
                        abase + (uint32_t)(mt*16*80 + kk*32));
            #pragma unroll
            for (int p = 0; p < 2; p++)
                ldsm_x4(rb[p][0], rb[p][1], rb[p][2], rb[p][3],
                        bbase + (uint32_t)(p*16*80 + kk*32));
            #pragma unroll
            for (int mt = 0; mt < 4; mt++)
                #pragma unroll
                for (int ng = 0; ng < 4; ng++)
                    mma16832(acc[mt][ng], ra[mt],
                             rb[ng>>1][ng&1], rb[ng>>1][(ng&1)+2]);
        }
    }
    __syncthreads();

    float scN = (MODE == 4) ? 3072.f : (float)N;
    float sc  = powf(sqrtf(scN) / log1pf(scN), alphap[0]);
    float sc2 = 0.f;
    if constexpr (MODE == 4) sc2 = powf(sqrtf(3072.f) / log1pf(3072.f), alphap2[0]);

    #pragma unroll
    for (int mt = 0; mt < 4; mt++) {
        #pragma unroll
        for (int half = 0; half < 2; half++) {
            int mloc = wm + mt*16 + (lane >> 2) + half*8;
            int m = m0 + mloc;
            float rnv = rn[m];
            #pragma unroll
            for (int ng = 0; ng < 4; ng++) {
                int nloc = wn + ng*8 + (lane & 3)*2;
                int n = n0 + nloc;
                float y0 = acc[mt][ng][half*2 + 0] * WSCALE_INV;
                float y1 = acc[mt][ng][half*2 + 1] * WSCALE_INV;
                float d0 = rnv + cns[nloc]   - 2.0f*y0 + 1e-6f;
                float d1 = rnv + cns[nloc+1] - 2.0f*y1 + 1e-6f;
                if constexpr (MODE == 4) {
                    int j = n >> 1;
                    float vfc = (y0*y0/d0 + bias[j])  * sc;
                    float vgt = (y1*y1/d1 + bias2[j]) * sc2;
                    out[(size_t)m*HID + j] = __float2bfloat16(gelu_tanh(vgt) * vfc);
                } else {
                    float v0 = (y0*y0/d0 + bias[n])   * sc;
                    float v1 = (y1*y1/d1 + bias[n+1]) * sc;
                    if (n < 2*Cc) {
                        int t  = m % Tt;
                        int dd = n & 63;
                        float f0 = extra[t*64 + dd], f1 = extra[t*64 + dd + 1];
                        if (n < Cc) { f0 *= 0.125f; f1 *= 0.125f; }
                        v0 *= f0; v1 *= f1;
                    }
                    *(__nv_bfloat162*)(out + (size_t)m*N + n) =
                        __floats2bfloat162_rn(v0, v1);
                }
            }
        }
    }
}

// ---------------- bf16 MODE-1 GEMM, BM=64 (for narrow N=768 GEMMs) --------------
// tile 64x128x32; 8 warps 2x4 of 32x32; grid (N/128, M/64) = 192 CTAs
#define GLDA 40
#define GLDB 136
#define GSTAGES 3

__global__ __launch_bounds__(256, 2)
void gemm_yat_mma1_b64(const __nv_bfloat16* __restrict__ A, const __nv_bfloat16* __restrict__ W,
                       float* __restrict__ out,
                       const float* __restrict__ part, int nch,
                       const float* __restrict__ bias, const float* __restrict__ alphap,
                       const float* __restrict__ extra,
                       int M, int N, int K)
{
    extern __shared__ __nv_bfloat16 smem[];
    __nv_bfloat16* As = smem;                         // GSTAGES * 64*GLDA
    __nv_bfloat16* Bs = smem + GSTAGES*64*GLDA;       // GSTAGES * 32*GLDB
    __shared__ float cns[128];
    __shared__ float cred[256];
    __shared__ float rns[64];

    const int tid = threadIdx.x;
    const int m0 = blockIdx.y * 64, n0 = blockIdx.x * 128;

    // A tile 64x32: row = tid>>2, 8-elem chunk (tid&3)
    const int a_row = tid >> 2, a_col = (tid & 3) * 8;
    const int b_row = tid >> 3, b_col = (tid & 7) * 16;
    const char* Ag = (const char*)(A + (size_t)(m0 + a_row) * K + a_col);
    const char* Bg = (const char*)(W + (size_t)b_row * N + n0 + b_col);
    const uint32_t As0 = (uint32_t)__cvta_generic_to_shared(As);
    const uint32_t Bs0 = (uint32_t)__cvta_generic_to_shared(Bs);
    const uint32_t Asw = As0 + (uint32_t)(a_row*GLDA + a_col)*2u;
    const uint32_t Bsw = Bs0 + (uint32_t)(b_row*GLDB + b_col)*2u;
    const uint32_t AS_STG = 64u*GLDA*2u, BS_STG = 32u*GLDB*2u;

    const int lane = tid & 31, warp = tid >> 5;
    const int wm = (warp >> 2) * 32;      // 0 / 32
    const int wn = (warp & 3) * 32;       // 0..96

    const int KT = K >> 5;

    auto issueT = [&](int kt, int stg) {
        const char* ag = Ag + (size_t)kt * 64;
        const char* bg = Bg + (size_t)kt * 32 * N * 2;
        uint32_t asd = Asw + (uint32_t)stg * AS_STG;
        uint32_t bsd = Bsw + (uint32_t)stg * BS_STG;
        cp_async16(asd, ag);
        cp_async16(bsd, bg);        cp_async16(bsd + 16u, bg + 16);
        cp_commit();
    };

    issueT(0, 0); issueT(1, 1);

    {
        int col  = tid & 127;
        int half = tid >> 7;
        float s = 0.f;
        for (int c = half; c < nch; c += 2)
            s += part[(size_t)c * N + n0 + col];
        cred[tid] = s;
    }
    __syncthreads();
    if (tid < 128) cns[tid] = cred[tid] + cred[tid + 128];

    float acc[2][4][4];
    #pragma unroll
    for (int i = 0; i < 2; i++)
        #pragma unroll
        for (int j = 0; j < 4; j++)
            #pragma unroll
            for (int e = 0; e < 4; e++) acc[i][j][e] = 0.f;

    const uint32_t a_mat = As0 + (uint32_t)(((wm + (lane & 15)) * GLDA) + (lane >> 4) * 8)*2u;
    const uint32_t b_mat = Bs0 + (uint32_t)(((lane & 15) * GLDB) + wn + (lane >> 4) * 8)*2u;

    float arn = 0.f;   // this thread's 8-elem chunk of row a_row

    int stg = 0, nstg = 2;
    for (int kt = 0; kt < KT; kt++) {
        if (kt + 1 < KT) cp_wait1(); else cp_wait0();
        __syncthreads();
        if (kt + 2 < KT) {
            issueT(kt + 2, nstg);
            nstg = (nstg == GSTAGES-1) ? 0 : nstg + 1;
        }

        {
            const __nv_bfloat16* ap = As + (size_t)stg*64*GLDA + a_row*GLDA + a_col;
            #pragma unroll
            for (int i = 0; i < 4; i++) {
                __nv_bfloat162 v2 = *(const __nv_bfloat162*)(ap + 2*i);
                float f0 = __bfloat162float(v2.x), f1 = __bfloat162float(v2.y);
                arn = fmaf(f0, f0, fmaf(f1, f1, arn));
            }
        }

        uint32_t abase = a_mat + (uint32_t)stg * AS_STG;
        uint32_t bbase = b_mat + (uint32_t)stg * BS_STG;
        stg = (stg == GSTAGES-1) ? 0 : stg + 1;
        #pragma unroll
        for (int kk = 0; kk < 2; kk++) {
            uint32_t ra[2][4];
            uint32_t rb[2][4];
            #pragma unroll
            for (int mt = 0; mt < 2; mt++)
                ldsm_x4(ra[mt][0], ra[mt][1], ra[mt][2], ra[mt][3],
                        abase + (uint32_t)(mt*16*GLDA + kk*16)*2u);
            #pragma unroll
            for (int p = 0; p < 2; p++)
                ldsm_x4_t(rb[p][0], rb[p][1], rb[p][2], rb[p][3],
                          bbase + (uint32_t)(kk*16*GLDB + p*16)*2u);
            #pragma unroll
            for (int mt = 0; mt < 2; mt++)
                #pragma unroll
                for (int nt = 0; nt < 4; nt++)
                    mma16816(acc[mt][nt], ra[mt],
                             rb[nt>>1][(nt&1)*2], rb[nt>>1][(nt&1)*2 + 1]);
        }
    }

    // combine the 4 chunk-partials of each row (threads tid&3 = 0..3)
    arn += __shfl_xor_sync(0xffffffffu, arn, 1);
    arn += __shfl_xor_sync(0xffffffffu, arn, 2);
    if ((tid & 3) == 0) rns[a_row] = arn;
    __syncthreads();

    float sc = powf(sqrtf((float)N) / log1pf((float)N), alphap[0]);
    #pragma unroll
    for (int mt = 0; mt < 2; mt++) {
        #pragma unroll
        for (int half = 0; half < 2; half++) {
            int mloc = wm + mt*16 + (lane >> 2) + half*8;
            int m = m0 + mloc;
            float rnv = rns[mloc];
            #pragma unroll
            for (int nt = 0; nt < 4; nt++) {
                int nloc = wn + nt*8 + (lane & 3)*2;
                int n = n0 + nloc;
                float y0 = acc[mt][nt][half*2 + 0];
                float y1 = acc[mt][nt][half*2 + 1];
                float d0 = rnv + cns[nloc]   - 2.0f*y0 + 1e-6f;
                float d1 = rnv + cns[nloc+1] - 2.0f*y1 + 1e-6f;
                float v0 = (y0*y0/d0 + bias[n])   * sc + extra[(size_t)m*N + n];
                float v1 = (y1*y1/d1 + bias[n+1]) * sc + extra[(size_t)m*N + n + 1];
                *(float2*)(out + (size_t)m*N + n) = make_float2(v0, v1);
            }
        }
    }
}

// ---------------- bf16 mma flash attention: 2-group split-KV, 256 threads -------
#define ALDK 72
__global__ __launch_bounds__(256)
void flash_attn_mma(const __nv_bfloat16* __restrict__ qkv, __nv_bfloat16* __restrict__ o)
{
    __shared__ __nv_bfloat16 KVs[4][64*ALDK];
    __shared__ float m1s[64], l1s[64];
    float* ovs = (float*)&KVs[2][0];

    const int tid  = threadIdx.x;
    const int g    = tid >> 7;
    const int gtid = tid & 127;
    const int lane = tid & 31, warp = tid >> 5;
    const int wg   = warp & 3;
    const int qt = (int)gridDim.x - 1 - (int)blockIdx.x;
    const int h = blockIdx.y, b = blockIdx.z;
    const int t0 = qt * 64;
    const int RS = 3*Cc;
    const int ng = (qt + 2 - g) >> 1;

    const int krow = gtid >> 1, koff = (gtid & 1) * 32;
    const __nv_bfloat16* kgbase = qkv + (size_t)(b*Tt + krow) * RS + Cc + h*64 + koff;
    const uint32_t kbL = (uint32_t)__cvta_generic_to_shared(&KVs[2*g][0]);
    const uint32_t vbL = (uint32_t)__cvta_generic_to_shared(&KVs[2*g+1][0]);
    const uint32_t ksw = kbL + (uint32_t)(krow*ALDK + koff)*2u;
    const uint32_t vsw = vbL + (uint32_t)(krow*ALDK + koff)*2u;

    auto issue = [&](int jt) {
        const __nv_bfloat16* kp = kgbase + (size_t)jt * 64 * RS;
        const __nv_bfloat16* vp = kp + Cc;
        #pragma unroll
        for (int i = 0; i < 4; i++) {
            cp_async16(ksw + i*16u, kp + i*8);
            cp_async16(vsw + i*16u, vp + i*8);
        }
        cp_commit();
    };

    if (ng > 0) issue(g);

    uint32_t qa[4][4];
    {
        int r = t0 + wg*16 + (lane >> 2);
        const __nv_bfloat16* q0 = qkv + (size_t)(b*Tt + r) * RS + h*64;
        const __nv_bfloat16* q8 = q0 + (size_t)8 * RS;
        #pragma unroll
        for (int kk = 0; kk < 4; kk++) {
            int c = kk*16 + (lane & 3)*2;
            qa[kk][0] = *(const uint32_t*)(q0 + c);
            qa[kk][1] = *(const uint32_t*)(q8 + c);
            qa[kk][2] = *(const uint32_t*)(q0 + c + 8);
            qa[kk][3] = *(const uint32_t*)(q8 + c + 8);
        }
    }

    float s[8][4], ov[8][4];
    float mrun[2] = {-1e30f, -1e30f}, lrun[2] = {0.f, 0.f};
    #pragma unroll
    for (int nt = 0; nt < 8; nt++)
        #pragma unroll
        for (int e = 0; e < 4; e++) ov[nt][e] = 0.f;

    const uint32_t kofs = (uint32_t)(((lane & 7) + ((lane >> 4) << 3)) * ALDK + (((lane >> 3) & 1) << 3)) * 2u;
    const uint32_t vofs = (uint32_t)((lane & 15) * ALDK + ((lane >> 4) << 3)) * 2u;

    for (int i = 0; i < ng; i++) {
        int jt = g + 2*i;
        cp_wait0();
        bar_sync(1 + g);

        #pragma unroll
        for (int nt = 0; nt < 8; nt++)
            #pragma unroll
            for (int e = 0; e < 4; e++) s[nt][e] = 0.f;
        uint32_t kb = kbL + kofs;
        #pragma unroll
        for (int kk = 0; kk < 4; kk++) {
            #pragma unroll
            for (int p = 0; p < 4; p++) {
                uint32_t r0, r1, r2, r3;
                ldsm_x4(r0, r1, r2, r3, kb + (uint32_t)(p*16*ALDK + kk*16)*2u);
                mma16816(s[2*p],   qa[kk], r0, r1);
                mma16816(s[2*p+1], qa[kk], r2, r3);
            }
        }

        bool diag = (jt == qt);
        #pragma unroll
        for (int half = 0; half < 2; half++) {
            int grow = t0 + wg*16 + (lane >> 2) + half*8;
            float mx = mrun[half];
            #pragma unroll
            for (int nt = 0; nt < 8; nt++) {
                float v0 = s[nt][half*2], v1 = s[nt][half*2+1];
                if (diag) {
                    int c0 = jt*64 + nt*8 + (lane & 3)*2;
                    if (c0     > grow) v0 = -1e30f;
                    if (c0 + 1 > grow) v1 = -1e30f;
                    s[nt][half*2] = v0; s[nt][half*2+1] = v1;
                }
                mx = fmaxf(mx, fmaxf(v0, v1));
            }
            mx = fmaxf(mx, __shfl_xor_sync(0xffffffffu, mx, 1));
            mx = fmaxf(mx, __shfl_xor_sync(0xffffffffu, mx, 2));
            float corr = __expf(mrun[half] - mx);
            mrun[half] = mx;
            float ls = 0.f;
            #pragma unroll
            for (int nt = 0; nt < 8; nt++) {
                float p0 = __expf(s[nt][half*2]   - mx);
                float p1 = __expf(s[nt][half*2+1] - mx);
                s[nt][half*2] = p0; s[nt][half*2+1] = p1;
                ls += p0 + p1;
            }
            ls += __shfl_xor_sync(0xffffffffu, ls, 1);
            ls += __shfl_xor_sync(0xffffffffu, ls, 2);
            lrun[half] = lrun[half]*corr + ls;
            #pragma unroll
            for (int nt = 0; nt < 8; nt++) { ov[nt][half*2] *= corr; ov[nt][half*2+1] *= corr; }
        }

        uint32_t pa[4][4];
        #pragma unroll
        for (int kk = 0; kk < 4; kk++) {
            pa[kk][0] = pack2(s[2*kk][0],   s[2*kk][1]);
            pa[kk][1] = pack2(s[2*kk][2],   s[2*kk][3]);
            pa[kk][2] = pack2(s[2*kk+1][0], s[2*kk+1][1]);
            pa[kk][3] = pack2(s[2*kk+1][2], s[2*kk+1][3]);
        }
        uint32_t vb = vbL + vofs;
        #pragma unroll
        for (int kk = 0; kk < 4; kk++) {
            #pragma unroll
            for (int p = 0; p < 4; p++) {
                uint32_t r0, r1, r2, r3;
                ldsm_x4_t(r0, r1, r2, r3, vb + (uint32_t)(kk*16*ALDK + p*16)*2u);
                mma16816(ov[2*p],   pa[kk], r0, r1);
                mma16816(ov[2*p+1], pa[kk], r2, r3);
            }
        }

        bar_sync(1 + g);
        if (i + 1 < ng) issue(g + 2*(i + 1));
    }

    __syncthreads();
    if (g == 1) {
        #pragma unroll
        for (int half = 0; half < 2; half++) {
            int rloc = wg*16 + (lane >> 2) + half*8;
            if ((lane & 3) == 0) { m1s[rloc] = mrun[half]; l1s[rloc] = lrun[half]; }
            #pragma unroll
            for (int nt = 0; nt < 8; nt++) {
                int c = nt*8 + (lane & 3)*2;
                ovs[rloc*65 + c]     = ov[nt][half*2];
                ovs[rloc*65 + c + 1] = ov[nt][half*2+1];
            }
        }
    }
    __syncthreads();
    if (g == 0) {
        #pragma unroll
        for (int half = 0; half < 2; half++) {
            int rloc = wg*16 + (lane >> 2) + half*8;
            float m1 = m1s[rloc], l1 = l1s[rloc];
            float ms = fmaxf(mrun[half], m1);
            float c0 = __expf(mrun[half] - ms);
            float c1 = __expf(m1 - ms);
            float inv = 1.0f / (lrun[half]*c0 + l1*c1);
            __nv_bfloat16* op = o + (size_t)(b*Tt + t0 + rloc)*Cc + h*64;
            #pragma unroll
            for (int nt = 0; nt < 8; nt++) {
                int c = nt*8 + (lane & 3)*2;
                float o0 = (ov[nt][half*2]  *c0 + ovs[rloc*65 + c]    *c1) * inv;
                float o1 = (ov[nt][half*2+1]*c0 + ovs[rloc*65 + c + 1]*c1) * inv;
                *(__nv_bfloat162*)(op + c) = __floats2bfloat162_rn(o0, o1);
            }
        }
    }
}

// ---------------- launch --------------------------------------------------------
extern "C" void kernel_launch(void* const* d_in, const int* in_sizes, int n_in,
                              void* d_out, int out_size)
{
    (void)in_sizes; (void)n_in; (void)out_size;
    const float* x      = (const float*)d_in[0];
    const float* ln1    = (const float*)d_in[2];
    const float* w_qkv  = (const float*)d_in[3];
    const float* b_qkv  = (const float*)d_in[4];
    const float* a_qkv  = (const float*)d_in[5];
    const float* w_ao   = (const float*)d_in[6];
    const float* b_ao   = (const float*)d_in[7];
    const float* a_ao   = (const float*)d_in[8];
    const float* ln2    = (const float*)d_in[9];
    const float* w_fc   = (const float*)d_in[10];
    const float* b_fc   = (const float*)d_in[11];
    const float* a_fc   = (const float*)d_in[12];
    const float* w_gate = (const float*)d_in[13];
    const float* b_gate = (const float*)d_in[14];
    const float* a_gate = (const float*)d_in[15];
    const float* w_proj = (const float*)d_in[16];
    const float* b_proj = (const float*)d_in[17];
    const float* a_proj = (const float*)d_in[18];
    float* out = (float*)d_out;

    float *x1, *rn, *part, *ropetab;
    __nv_bfloat16 *qkvb, *o, *u, *wao, *wp;
    __nv_fp8_e4m3 *h, *h2, *wq8, *wfcg8;
    cudaGetSymbolAddress((void**)&x1,     g_x1);
    cudaGetSymbolAddress((void**)&rn,     g_rn);
    cudaGetSymbolAddress((void**)&part,   g_part);
    cudaGetSymbolAddress((void**)&ropetab,g_rope);
    cudaGetSymbolAddress((void**)&qkvb,   g_qkvb);
    cudaGetSymbolAddress((void**)&h,      g_h);
    cudaGetSymbolAddress((void**)&o,      g_o);
    cudaGetSymbolAddress((void**)&h2,     g_h2);
    cudaGetSymbolAddress((void**)&u,      g_u);
    cudaGetSymbolAddress((void**)&wq8,    g_wq8);
    cudaGetSymbolAddress((void**)&wao,    g_wao);
    cudaGetSymbolAddress((void**)&wfcg8,  g_wfcg8);
    cudaGetSymbolAddress((void**)&wp,     g_wp);

    const int GSMEM64 = GSTAGES * (64*GLDA + 32*GLDB) * (int)sizeof(__nv_bfloat16);
    const int F8SMEM  = F8STAGES * 2 * (int)F8STGB;
    cudaFuncSetAttribute(gemm_yat_mma1_b64,
                         cudaFuncAttributeMaxDynamicSharedMemorySize, GSMEM64);
    cudaFuncSetAttribute(gemm_yat_fp8<3>,
                         cudaFuncAttributeMaxDynamicSharedMemorySize, F8SMEM);
    cudaFuncSetAttribute(gemm_yat_fp8<4>,
                         cudaFuncAttributeMaxDynamicSharedMemorySize, F8SMEM);

    // 0. all weight conversions + colnorm partials + rope table (one launch)
    wconv_all<<<2560, 256>>>(w_qkv, w_ao, w_fc, w_gate, w_proj,
                             wq8, wao, wfcg8, wp, part, ropetab);

    // 1. LN1 -> h (fp8), rn
    ln_kernel<<<Mrows, 256>>>(x, ln1, h, rn);

    // 2. qkv = rope(yat(h @ w_qkv)) bf16, q pre-scaled by 1/8   [fp8 GEMM]
    gemm_yat_fp8<3><<<dim3(3*Cc/128, Mrows/128), 256, F8SMEM>>>(
        h, wq8, qkvb, rn, part + PART_QKV, Cc/64, b_qkv, a_qkv, nullptr, nullptr,
        ropetab, Mrows, 3*Cc, Cc);

    // 3. attention -> o (bf16)
    flash_attn_mma<<<dim3(Tt/64, Hh, Bb), 256>>>(qkvb, o);

    // 4. x1 = x + yat(o @ w_ao)   [bf16 BM=64 GEMM: 192 CTAs]
    gemm_yat_mma1_b64<<<dim3(Cc/128, Mrows/64), 256, GSMEM64>>>(
        o, wao, x1, part + PART_AO, Cc/64, b_ao, a_ao, x, Mrows, Cc, Cc);

    // 5. LN2 -> h2 (fp8), rn
    ln_kernel<<<Mrows, 256>>>(x1, ln2, h2, rn);

    // 6+7. u = gelu(yat(h2@w_gate)) * yat(h2@w_fc)   [fp8 interleaved GEMM]
    gemm_yat_fp8<4><<<dim3(NFCG/128, Mrows/128), 256, F8SMEM>>>(
        h2, wfcg8, u, rn, part + PART_FCG, Cc/64, b_fc, a_fc, b_gate, a_gate,
        (const float*)nullptr, Mrows, NFCG, Cc);

    // 8. out = x1 + yat(u @ w_proj)   [bf16 BM=64 GEMM: 192 CTAs]
    gemm_yat_mma1_b64<<<dim3(Cc/128, Mrows/64), 256, GSMEM64>>>(
        u, wp, out, part + PART_PROJ, HID/64, b_proj, a_proj, x1, Mrows, Cc, HID);
}